// round 1
// baseline (speedup 1.0000x reference)
#include <cuda_runtime.h>
#include <math.h>
#include <float.h>

#define BB 8
#define NN 1024
#define KNN 20

// ---------------- static device scratch (no allocations allowed) ----------------
__device__ float  g_G[(size_t)BB*NN*NN];        // 32MB pairwise dot
__device__ float  g_SQ[BB*NN];
__device__ int    g_IDX[BB*NN*KNN];
__device__ float  g_FEAT[(size_t)BB*NN*512];    // concatenated features (b,n,c)
__device__ float  g_YMAX[(size_t)BB*NN*256];    // pre-norm max over k
__device__ float  g_YMIN[(size_t)BB*NN*256];    // pre-norm min over k
__device__ double g_SUM[512];
__device__ double g_SUMSQ[512];
__device__ float  g_A[512];
__device__ float  g_Cc[512];
__device__ float  g_WC[45248];                  // precomputed (w[:,C:]-w[:,:C]) per block
__device__ float  g_Y5[(size_t)BB*512*NN];      // final conv activations (b,o,n)
__device__ float  g_MX[BB*512];
__device__ float  g_MN[BB*512];

// ---------------- prep: center-weight differences for all 4 blocks ----------------
__global__ void prep_kernel(const float* __restrict__ w1, const float* __restrict__ w2,
                            const float* __restrict__ w3, const float* __restrict__ w4) {
    int t = blockIdx.x * blockDim.x + threadIdx.x;
    if (t < 192) { int o = t/3,  c = t%3;   g_WC[t]        = w1[o*6   + 3   + c] - w1[o*6   + c]; return; }
    int u = t - 192;
    if (u < 4096) { int o = u/64, c = u%64; g_WC[192 + u]  = w2[o*128 + 64  + c] - w2[o*128 + c]; return; }
    u -= 4096;
    if (u < 8192) { int o = u/64, c = u%64; g_WC[4288 + u] = w3[o*128 + 64  + c] - w3[o*128 + c]; return; }
    u -= 8192;
    if (u < 32768){ int o = u/128,c = u%128;g_WC[12480 + u]= w4[o*256 + 128 + c] - w4[o*256 + c]; return; }
}

// ---------------- squared norms ----------------
template<int C>
__global__ void sq_kernel(const float* __restrict__ X, int ld, int off) {
    int i = blockIdx.x * blockDim.x + threadIdx.x;
    if (i >= BB*NN) return;
    const float* p = X + (size_t)i*ld + off;
    float s = 0.f;
    #pragma unroll
    for (int c = 0; c < C; c++) s = fmaf(p[c], p[c], s);
    g_SQ[i] = s;
}

// ---------------- gram: G[b][n][m] = dot(X[b,n], X[b,m]) ----------------
template<int C>
__global__ void gram_kernel(const float* __restrict__ X, int ld, int off) {
    constexpr int TC = (C < 32) ? C : 32;
    __shared__ float As[64][TC+1];
    __shared__ float Bs[64][TC+1];
    int b  = blockIdx.z;
    int m0 = blockIdx.x * 64, n0 = blockIdx.y * 64;
    int tx = threadIdx.x & 15, ty = threadIdx.x >> 4;
    float acc[4][4];
    #pragma unroll
    for (int i = 0; i < 4; i++)
        #pragma unroll
        for (int j = 0; j < 4; j++) acc[i][j] = 0.f;

    for (int c0 = 0; c0 < C; c0 += TC) {
        for (int i = threadIdx.x; i < 64*TC; i += 256) {
            int r = i / TC, c = i - r*TC;
            As[r][c] = X[(size_t)(b*NN + n0 + r)*ld + off + c0 + c];
            Bs[r][c] = X[(size_t)(b*NN + m0 + r)*ld + off + c0 + c];
        }
        __syncthreads();
        for (int c = 0; c < TC; c++) {
            float av[4], bv[4];
            #pragma unroll
            for (int i = 0; i < 4; i++) { av[i] = As[ty*4+i][c]; bv[i] = Bs[tx*4+i][c]; }
            #pragma unroll
            for (int i = 0; i < 4; i++)
                #pragma unroll
                for (int j = 0; j < 4; j++) acc[i][j] = fmaf(av[i], bv[j], acc[i][j]);
        }
        __syncthreads();
    }
    #pragma unroll
    for (int i = 0; i < 4; i++)
        #pragma unroll
        for (int j = 0; j < 4; j++)
            g_G[((size_t)(b*NN) + n0 + ty*4 + i)*NN + m0 + tx*4 + j] = acc[i][j];
}

// ---------------- top-k=20 per row (lowest-index tie-break, matches lax.top_k) ----------------
__global__ void topk_kernel() {
    __shared__ float vals[NN];
    __shared__ float wv[8];
    __shared__ int   wi[8];
    int bn = blockIdx.x;
    int b  = bn >> 10;
    const float* grow = g_G  + (size_t)bn * NN;
    const float* sq   = g_SQ + b * NN;
    int t = threadIdx.x;
    for (int m = t; m < NN; m += 256) vals[m] = 2.f*grow[m] - sq[m];
    __syncthreads();
    for (int j = 0; j < KNN; j++) {
        float bv = -FLT_MAX; int bi = NN;
        for (int m = t; m < NN; m += 256) {
            float v = vals[m];
            if (v > bv) { bv = v; bi = m; }   // ascending scan -> lowest index kept on tie
        }
        for (int s = 16; s; s >>= 1) {
            float ov = __shfl_down_sync(0xFFFFFFFFu, bv, s);
            int   oi = __shfl_down_sync(0xFFFFFFFFu, bi, s);
            if (ov > bv || (ov == bv && oi < bi)) { bv = ov; bi = oi; }
        }
        if ((t & 31) == 0) { wv[t>>5] = bv; wi[t>>5] = bi; }
        __syncthreads();
        if (t == 0) {
            for (int w = 1; w < 8; w++)
                if (wv[w] > bv || (wv[w] == bv && wi[w] < bi)) { bv = wv[w]; bi = wi[w]; }
            g_IDX[bn*KNN + j] = bi;
            vals[bi] = -FLT_MAX;
        }
        __syncthreads();
    }
}

__global__ void zero_stats_kernel() {
    int o = threadIdx.x;
    if (o < 512) { g_SUM[o] = 0.0; g_SUMSQ[o] = 0.0; }
}

// ---------------- fused gather + edge conv + stats + k-max/min ----------------
// y[o,col] = Wn[o,:].neigh_col + WC[o,:].ctr ; 2 points per block, 40 cols.
template<int C, int O>
__global__ void conv_kernel(const float* __restrict__ Xin, int ld, int off,
                            const float* __restrict__ w, const float* __restrict__ wc) {
    constexpr int TC = (C < 32) ? C : 32;
    constexpr int Cp = C + 1;
    constexpr int NO = O / 32;
    extern __shared__ float sm[];
    float* nsh = sm;                 // [40][Cp]
    float* csh = nsh + 40*Cp;        // [2][C]
    float* wt  = csh + 2*C;          // [O][TC+1]

    int blk = blockIdx.x;
    int b   = blk >> 9;              // 512 blocks per batch
    int n0  = (blk & 511) << 1;
    int t   = threadIdx.x;
    int olane = t >> 3;
    int clane = t & 7;
    int myp   = clane >> 2;          // clanes 0-3 -> point 0, 4-7 -> point 1

    for (int i = t; i < 40*C; i += 256) {
        int col = i / C, c = i - col*C;
        int p = col / KNN, jj = col - p*KNN;
        int m = g_IDX[(b*NN + n0 + p)*KNN + jj];
        nsh[col*Cp + c] = Xin[(size_t)(b*NN + m)*ld + off + c];
    }
    for (int i = t; i < 2*C; i += 256) {
        int p = i / C, c = i - p*C;
        csh[i] = Xin[(size_t)(b*NN + n0 + p)*ld + off + c];
    }

    float acc[NO][5];
    float tctr[NO];
    #pragma unroll
    for (int oo = 0; oo < NO; oo++) {
        tctr[oo] = 0.f;
        #pragma unroll
        for (int cc = 0; cc < 5; cc++) acc[oo][cc] = 0.f;
    }

    // neighbor GEMM, weight tiles staged in shared
    for (int c0 = 0; c0 < C; c0 += TC) {
        __syncthreads();
        for (int i = t; i < O*TC; i += 256) {
            int o = i / TC, ct = i - o*TC;
            wt[o*(TC+1) + ct] = w[(size_t)o*(2*C) + c0 + ct];
        }
        __syncthreads();
        for (int ct = 0; ct < TC; ct++) {
            int c = c0 + ct;
            float nv[5];
            #pragma unroll
            for (int cc = 0; cc < 5; cc++) nv[cc] = nsh[(clane*5 + cc)*Cp + c];
            #pragma unroll
            for (int oo = 0; oo < NO; oo++) {
                float wvv = wt[(oo*32 + olane)*(TC+1) + ct];
                #pragma unroll
                for (int cc = 0; cc < 5; cc++) acc[oo][cc] = fmaf(wvv, nv[cc], acc[oo][cc]);
            }
        }
    }
    // center term (stage WC tiles in same buffer)
    for (int c0 = 0; c0 < C; c0 += TC) {
        __syncthreads();
        for (int i = t; i < O*TC; i += 256) {
            int o = i / TC, ct = i - o*TC;
            wt[o*(TC+1) + ct] = wc[(size_t)o*C + c0 + ct];
        }
        __syncthreads();
        for (int ct = 0; ct < TC; ct++) {
            float cv = csh[myp*C + c0 + ct];
            #pragma unroll
            for (int oo = 0; oo < NO; oo++)
                tctr[oo] = fmaf(wt[(oo*32 + olane)*(TC+1) + ct], cv, tctr[oo]);
        }
    }

    int n_pt = n0 + myp;
    #pragma unroll
    for (int oo = 0; oo < NO; oo++) {
        int o = oo*32 + olane;
        float mx = -FLT_MAX, mn = FLT_MAX, s = 0.f, s2 = 0.f;
        #pragma unroll
        for (int cc = 0; cc < 5; cc++) {
            float y = acc[oo][cc] + tctr[oo];
            mx = fmaxf(mx, y); mn = fminf(mn, y);
            s += y; s2 = fmaf(y, y, s2);
        }
        for (int sft = 4; sft; sft >>= 1) {
            s  += __shfl_down_sync(0xFFFFFFFFu, s,  sft, 8);
            s2 += __shfl_down_sync(0xFFFFFFFFu, s2, sft, 8);
        }
        for (int sft = 2; sft; sft >>= 1) {
            mx = fmaxf(mx, __shfl_down_sync(0xFFFFFFFFu, mx, sft, 4));
            mn = fminf(mn, __shfl_down_sync(0xFFFFFFFFu, mn, sft, 4));
        }
        if ((clane & 3) == 0) {
            g_YMAX[(size_t)(b*NN + n_pt)*O + o] = mx;
            g_YMIN[(size_t)(b*NN + n_pt)*O + o] = mn;
        }
        if (clane == 0) {
            atomicAdd(&g_SUM[o],   (double)s);
            atomicAdd(&g_SUMSQ[o], (double)s2);
        }
    }
}

// ---------------- BN affine coefficients ----------------
__global__ void stats_kernel(const float* __restrict__ g, const float* __restrict__ beta,
                             float count, int O) {
    int o = threadIdx.x;
    if (o >= O) return;
    double m   = g_SUM[o]   / (double)count;
    double var = g_SUMSQ[o] / (double)count - m*m;
    float a = g[o] / sqrtf((float)var + 1e-5f);
    g_A[o]  = a;
    g_Cc[o] = beta[o] - (float)m * a;
}

// ---------------- apply norm+lrelu to max-pooled values, write concat features ----------------
__global__ void apply_kernel(int O, int outOff) {
    int i = blockIdx.x * blockDim.x + threadIdx.x;
    if (i >= BB*NN*O) return;
    int o  = i % O;
    int bn = i / O;
    float a = g_A[o], c = g_Cc[o];
    float sel = (a >= 0.f) ? g_YMAX[i] : g_YMIN[i];
    float v = fmaf(a, sel, c);
    g_FEAT[(size_t)bn*512 + outOff + o] = (v >= 0.f) ? v : 0.2f*v;
}

// ---------------- final 512x512 1x1 conv + stats ----------------
__global__ void gemm5_kernel(const float* __restrict__ w5) {
    constexpr int PB = 16, TC = 16, O = 512, C = 512, NO = 16, Cp = C + 1;
    extern __shared__ float sm[];
    float* cols = sm;                 // [PB][Cp]
    float* wt   = sm + PB*Cp;         // [O][TC+1]
    int blk = blockIdx.x;             // 512 blocks
    int b   = blk >> 6;
    int n0  = (blk & 63) * PB;
    int t   = threadIdx.x;
    int olane = t >> 3, clane = t & 7;

    for (int i = t; i < PB*C; i += 256) {
        int p = i >> 9, c = i & 511;
        cols[p*Cp + c] = g_FEAT[(size_t)(b*NN + n0 + p)*512 + c];
    }
    float acc[NO][2];
    #pragma unroll
    for (int oo = 0; oo < NO; oo++) { acc[oo][0] = 0.f; acc[oo][1] = 0.f; }

    for (int c0 = 0; c0 < C; c0 += TC) {
        __syncthreads();
        for (int i = t; i < O*TC; i += 256) {
            int o = i >> 4, ct = i & 15;
            wt[o*(TC+1) + ct] = w5[(size_t)o*512 + c0 + ct];
        }
        __syncthreads();
        for (int ct = 0; ct < TC; ct++) {
            int c = c0 + ct;
            float cv0 = cols[(clane*2 + 0)*Cp + c];
            float cv1 = cols[(clane*2 + 1)*Cp + c];
            #pragma unroll
            for (int oo = 0; oo < NO; oo++) {
                float wvv = wt[(oo*32 + olane)*(TC+1) + ct];
                acc[oo][0] = fmaf(wvv, cv0, acc[oo][0]);
                acc[oo][1] = fmaf(wvv, cv1, acc[oo][1]);
            }
        }
    }
    #pragma unroll
    for (int oo = 0; oo < NO; oo++) {
        int o = oo*32 + olane;
        float y0 = acc[oo][0], y1 = acc[oo][1];
        int n = n0 + clane*2;
        g_Y5[((size_t)b*O + o)*NN + n]     = y0;
        g_Y5[((size_t)b*O + o)*NN + n + 1] = y1;
        float s = y0 + y1, s2 = y0*y0 + y1*y1;
        for (int sft = 4; sft; sft >>= 1) {
            s  += __shfl_down_sync(0xFFFFFFFFu, s,  sft, 8);
            s2 += __shfl_down_sync(0xFFFFFFFFu, s2, sft, 8);
        }
        if (clane == 0) {
            atomicAdd(&g_SUM[o],   (double)s);
            atomicAdd(&g_SUMSQ[o], (double)s2);
        }
    }
}

// ---------------- per (b,o) max/min over n ----------------
__global__ void reduce5_kernel() {
    __shared__ float smx[8], smn[8];
    int row = blockIdx.x;
    const float* p = g_Y5 + (size_t)row * NN;
    float mx = -FLT_MAX, mn = FLT_MAX;
    for (int i = threadIdx.x; i < NN; i += 256) {
        float v = p[i];
        mx = fmaxf(mx, v); mn = fminf(mn, v);
    }
    for (int s = 16; s; s >>= 1) {
        mx = fmaxf(mx, __shfl_down_sync(0xFFFFFFFFu, mx, s));
        mn = fminf(mn, __shfl_down_sync(0xFFFFFFFFu, mn, s));
    }
    if ((threadIdx.x & 31) == 0) { smx[threadIdx.x >> 5] = mx; smn[threadIdx.x >> 5] = mn; }
    __syncthreads();
    if (threadIdx.x == 0) {
        float M = smx[0], m_ = smn[0];
        for (int w = 1; w < 8; w++) { M = fmaxf(M, smx[w]); m_ = fminf(m_, smn[w]); }
        g_MX[row] = M; g_MN[row] = m_;
    }
}

// ---------------- final norm + global max + embedding ----------------
__global__ void emb_kernel(const float* __restrict__ wemb, float* __restrict__ out) {
    __shared__ float feat[512];
    int b = blockIdx.x, t = threadIdx.x;
    for (int o = t; o < 512; o += 256) {
        float a = g_A[o], c = g_Cc[o];
        float sel = (a >= 0.f) ? g_MX[b*512 + o] : g_MN[b*512 + o];
        float v = fmaf(a, sel, c);
        feat[o] = (v >= 0.f) ? v : 0.2f*v;
    }
    __syncthreads();
    const float* wr = wemb + (size_t)t * 512;
    float s = 0.f;
    for (int c = 0; c < 512; c++) s = fmaf(wr[c], feat[c], s);
    out[b*256 + t] = s;
}

// ---------------- host orchestration ----------------
static size_t conv_smem_bytes(int C, int O) {
    int TC = (C < 32) ? C : 32;
    return (size_t)(40*(C+1) + 2*C + O*(TC+1)) * 4;
}

template<int C, int O>
static void run_edge(const float* X, int ld, int off, const float* w, const float* wc,
                     const float* g, const float* beta, int outOff) {
    sq_kernel<C><<<(BB*NN + 255)/256, 256>>>(X, ld, off);
    dim3 gg(NN/64, NN/64, BB);
    gram_kernel<C><<<gg, 256>>>(X, ld, off);
    topk_kernel<<<BB*NN, 256>>>();
    zero_stats_kernel<<<1, 512>>>();
    conv_kernel<C, O><<<BB*NN/2, 256, conv_smem_bytes(C, O)>>>(X, ld, off, w, wc);
    stats_kernel<<<1, 512>>>(g, beta, (float)(BB*NN*KNN), O);
    apply_kernel<<<(BB*NN*O + 255)/256, 256>>>(O, outOff);
}

extern "C" void kernel_launch(void* const* d_in, const int* in_sizes, int n_in,
                              void* d_out, int out_size) {
    (void)in_sizes; (void)n_in; (void)out_size;
    const float* x    = (const float*)d_in[0];
    const float* w1   = (const float*)d_in[1];
    const float* g1   = (const float*)d_in[2];
    const float* b1   = (const float*)d_in[3];
    const float* w2   = (const float*)d_in[4];
    const float* g2   = (const float*)d_in[5];
    const float* b2   = (const float*)d_in[6];
    const float* w3   = (const float*)d_in[7];
    const float* g3   = (const float*)d_in[8];
    const float* b3   = (const float*)d_in[9];
    const float* w4   = (const float*)d_in[10];
    const float* g4   = (const float*)d_in[11];
    const float* b4   = (const float*)d_in[12];
    const float* w5   = (const float*)d_in[13];
    const float* g5   = (const float*)d_in[14];
    const float* b5   = (const float*)d_in[15];
    const float* wemb = (const float*)d_in[16];
    float* out = (float*)d_out;

    float *feat, *wcb;
    cudaGetSymbolAddress((void**)&feat, g_FEAT);
    cudaGetSymbolAddress((void**)&wcb,  g_WC);

    cudaFuncSetAttribute(conv_kernel<128, 256>,
                         cudaFuncAttributeMaxDynamicSharedMemorySize, 60000);
    cudaFuncSetAttribute(gemm5_kernel,
                         cudaFuncAttributeMaxDynamicSharedMemorySize, 70000);

    prep_kernel<<<(45248 + 255)/256, 256>>>(w1, w2, w3, w4);

    run_edge<3,   64 >(x,    3,   0,   w1, wcb + 0,     g1, b1, 0);
    run_edge<64,  64 >(feat, 512, 0,   w2, wcb + 192,   g2, b2, 64);
    run_edge<64,  128>(feat, 512, 64,  w3, wcb + 4288,  g3, b3, 128);
    run_edge<128, 256>(feat, 512, 128, w4, wcb + 12480, g4, b4, 256);

    zero_stats_kernel<<<1, 512>>>();
    gemm5_kernel<<<512, 256, (16*513 + 512*17) * 4>>>(w5);
    reduce5_kernel<<<BB*512, 256>>>();
    stats_kernel<<<1, 512>>>(g5, b5, (float)(BB*NN), 512);
    emb_kernel<<<BB, 256>>>(wemb, out);
}

// round 2
// speedup vs baseline: 1.9614x; 1.9614x over previous
#include <cuda_runtime.h>
#include <math.h>
#include <float.h>

#define BB 8
#define NN 1024
#define KNN 20

// ---------------- static device scratch ----------------
__device__ float  g_G[(size_t)BB*NN*NN];        // pairwise 2*dot - sq[m]
__device__ float  g_SQ[BB*NN];
__device__ int    g_IDX[BB*NN*KNN];
__device__ float  g_Z2[(size_t)BB*NN*512];      // [bn][2O]: Zn | Zc
__device__ float  g_FEAT[(size_t)BB*NN*512];    // concat features (bn, c)
__device__ float  g_YMAX[(size_t)BB*NN*256];    // pre-norm max over k
__device__ float  g_YMIN[(size_t)BB*NN*256];
__device__ double g_SUM[512];
__device__ double g_SUMSQ[512];
__device__ float  g_A[512];
__device__ float  g_Cc[512];
__device__ float  g_WCAT[90496];                // per-block [Wn ; Wc-Wn] rows
__device__ float  g_Y5[(size_t)BB*512*NN];      // final conv (b,o,n)
__device__ float  g_MX[BB*512];
__device__ float  g_MN[BB*512];

// WCAT offsets: b1:0 (128x3), b2:384 (128x64), b3:8576 (256x64), b4:24960 (512x128)

__global__ void prep_kernel(const float* __restrict__ w1, const float* __restrict__ w2,
                            const float* __restrict__ w3, const float* __restrict__ w4) {
    int t = blockIdx.x * blockDim.x + threadIdx.x;
    if (t < 384) {
        int r = t/3, c = t%3;
        g_WCAT[t] = (r < 64) ? w1[r*6 + c] : (w1[(r-64)*6 + 3 + c] - w1[(r-64)*6 + c]);
        return;
    }
    int u = t - 384;
    if (u < 8192) {
        int r = u/64, c = u%64;
        g_WCAT[384 + u] = (r < 64) ? w2[r*128 + c] : (w2[(r-64)*128 + 64 + c] - w2[(r-64)*128 + c]);
        return;
    }
    u -= 8192;
    if (u < 16384) {
        int r = u/64, c = u%64;
        g_WCAT[8576 + u] = (r < 128) ? w3[r*128 + c] : (w3[(r-128)*128 + 64 + c] - w3[(r-128)*128 + c]);
        return;
    }
    u -= 16384;
    if (u < 65536) {
        int r = u/128, c = u%128;
        g_WCAT[24960 + u] = (r < 256) ? w4[r*256 + c] : (w4[(r-256)*256 + 128 + c] - w4[(r-256)*256 + c]);
        return;
    }
}

// ---------------- squared norms ----------------
template<int C>
__global__ void sq_kernel(const float* __restrict__ X, int ld, int off) {
    int i = blockIdx.x * blockDim.x + threadIdx.x;
    if (i >= BB*NN) return;
    const float* p = X + (size_t)i*ld + off;
    float s = 0.f;
    #pragma unroll
    for (int c = 0; c < C; c++) s = fmaf(p[c], p[c], s);
    g_SQ[i] = s;
}

// ---------------- gram with fused ranking value: G[n][m] = 2*dot - sq[m] ----------------
template<int C>
__global__ void gram_kernel(const float* __restrict__ X, int ld, int off) {
    constexpr int TC = (C < 32) ? C : 32;
    __shared__ float As[64][TC+1];
    __shared__ float Bs[64][TC+1];
    int b  = blockIdx.z;
    int m0 = blockIdx.x * 64, n0 = blockIdx.y * 64;
    int tx = threadIdx.x & 15, ty = threadIdx.x >> 4;
    float acc[4][4];
    #pragma unroll
    for (int i = 0; i < 4; i++)
        #pragma unroll
        for (int j = 0; j < 4; j++) acc[i][j] = 0.f;

    for (int c0 = 0; c0 < C; c0 += TC) {
        for (int i = threadIdx.x; i < 64*TC; i += 256) {
            int r = i / TC, c = i - r*TC;
            As[r][c] = X[(size_t)(b*NN + n0 + r)*ld + off + c0 + c];
            Bs[r][c] = X[(size_t)(b*NN + m0 + r)*ld + off + c0 + c];
        }
        __syncthreads();
        for (int c = 0; c < TC; c++) {
            float av[4], bv[4];
            #pragma unroll
            for (int i = 0; i < 4; i++) { av[i] = As[ty*4+i][c]; bv[i] = Bs[tx*4+i][c]; }
            #pragma unroll
            for (int i = 0; i < 4; i++)
                #pragma unroll
                for (int j = 0; j < 4; j++) acc[i][j] = fmaf(av[i], bv[j], acc[i][j]);
        }
        __syncthreads();
    }
    float sqv[4];
    #pragma unroll
    for (int j = 0; j < 4; j++) sqv[j] = g_SQ[b*NN + m0 + tx*4 + j];
    #pragma unroll
    for (int i = 0; i < 4; i++)
        #pragma unroll
        for (int j = 0; j < 4; j++)
            g_G[((size_t)(b*NN) + n0 + ty*4 + i)*NN + m0 + tx*4 + j] = 2.f*acc[i][j] - sqv[j];
}

// ---------------- top-20: one warp per row, values in registers ----------------
__global__ void topk_kernel() {
    int warp = (blockIdx.x << 3) + (threadIdx.x >> 5);   // row = bn
    int l = threadIdx.x & 31;
    const float* grow = g_G + (size_t)warp * NN;
    float v[32];
    #pragma unroll
    for (int s = 0; s < 32; s++) v[s] = grow[s*32 + l];
    float lmax = -FLT_MAX; int lslot = 0;
    #pragma unroll
    for (int s = 0; s < 32; s++) if (v[s] > lmax) { lmax = v[s]; lslot = s; }

    for (int j = 0; j < KNN; j++) {
        float bv = lmax;
        int   bm = (lslot << 5) | l;
        #pragma unroll
        for (int o = 16; o; o >>= 1) {
            float ov = __shfl_xor_sync(0xFFFFFFFFu, bv, o);
            int   om = __shfl_xor_sync(0xFFFFFFFFu, bm, o);
            if (ov > bv || (ov == bv && om < bm)) { bv = ov; bm = om; }
        }
        if (l == 0) g_IDX[warp*KNN + j] = bm;
        int owner = bm & 31, slot = bm >> 5;
        if (l == owner) {
            #pragma unroll
            for (int s = 0; s < 32; s++) if (s == slot) v[s] = -FLT_MAX;
            lmax = -FLT_MAX; lslot = 0;
            #pragma unroll
            for (int s = 0; s < 32; s++) if (v[s] > lmax) { lmax = v[s]; lslot = s; }
        }
    }
}

__global__ void zero_stats_kernel() {
    int o = threadIdx.x;
    if (o < 512) { g_SUM[o] = 0.0; g_SUMSQ[o] = 0.0; }
}

// ---------------- Z GEMM: Z2[bn][0..2O) = X[bn,:] . Wcat[o,:]^T ----------------
template<int C, int N2>
__global__ void zgemm_kernel(const float* __restrict__ X, int ld, int off,
                             const float* __restrict__ W) {
    constexpr int TC = (C < 32) ? C : 32;
    __shared__ float As[64][TC+1];
    __shared__ float Bs[64][TC+1];
    int r0 = blockIdx.x * 64;
    int o0 = blockIdx.y * 64;
    int tx = threadIdx.x & 15, ty = threadIdx.x >> 4;
    float acc[4][4];
    #pragma unroll
    for (int i = 0; i < 4; i++)
        #pragma unroll
        for (int j = 0; j < 4; j++) acc[i][j] = 0.f;

    for (int c0 = 0; c0 < C; c0 += TC) {
        for (int i = threadIdx.x; i < 64*TC; i += 256) {
            int r = i / TC, c = i - r*TC;
            As[r][c] = X[(size_t)(r0 + r)*ld + off + c0 + c];
            Bs[r][c] = W[(size_t)(o0 + r)*C + c0 + c];
        }
        __syncthreads();
        for (int c = 0; c < TC; c++) {
            float av[4], bv[4];
            #pragma unroll
            for (int i = 0; i < 4; i++) { av[i] = As[ty*4+i][c]; bv[i] = Bs[tx*4+i][c]; }
            #pragma unroll
            for (int i = 0; i < 4; i++)
                #pragma unroll
                for (int j = 0; j < 4; j++) acc[i][j] = fmaf(av[i], bv[j], acc[i][j]);
        }
        __syncthreads();
    }
    #pragma unroll
    for (int i = 0; i < 4; i++)
        #pragma unroll
        for (int j = 0; j < 4; j++)
            g_Z2[(size_t)(r0 + ty*4 + i)*N2 + o0 + tx*4 + j] = acc[i][j];
}

// ---------------- gather + k-reduce: 8 points per block ----------------
template<int O>
__global__ void gather_kernel() {
    constexpr int PL = 256 / O;           // point lanes
    __shared__ int sidx[8*KNN];
    int n0 = blockIdx.x * 8;              // global bn base (same batch for all 8)
    int b  = n0 >> 10;
    int t  = threadIdx.x;
    for (int i = t; i < 8*KNN; i += 256) sidx[i] = g_IDX[n0*KNN + i];
    __syncthreads();

    int ch = t & (O - 1);
    int pl = t / O;
    const float* Zb = g_Z2 + ((size_t)b << 10) * (2*O);
    float S = 0.f, S2 = 0.f;
    for (int p = pl; p < 8; p += PL) {
        int n = n0 + p;
        float ctr = g_Z2[(size_t)n*(2*O) + O + ch];
        float mx = -FLT_MAX, mn = FLT_MAX, sz = 0.f, sz2 = 0.f;
        #pragma unroll
        for (int j = 0; j < KNN; j++) {
            int m = sidx[p*KNN + j];
            float z = Zb[(size_t)m*(2*O) + ch];
            mx = fmaxf(mx, z); mn = fminf(mn, z);
            sz += z; sz2 = fmaf(z, z, sz2);
        }
        g_YMAX[(size_t)n*O + ch] = mx + ctr;
        g_YMIN[(size_t)n*O + ch] = mn + ctr;
        S  += sz + (float)KNN * ctr;
        S2 += sz2 + 2.f*ctr*sz + (float)KNN * ctr * ctr;
    }
    atomicAdd(&g_SUM[ch],   (double)S);
    atomicAdd(&g_SUMSQ[ch], (double)S2);
}

// ---------------- BN affine coefficients ----------------
__global__ void stats_kernel(const float* __restrict__ g, const float* __restrict__ beta,
                             float count, int O) {
    int o = threadIdx.x;
    if (o >= O) return;
    double m   = g_SUM[o]   / (double)count;
    double var = g_SUMSQ[o] / (double)count - m*m;
    float a = g[o] / sqrtf((float)var + 1e-5f);
    g_A[o]  = a;
    g_Cc[o] = beta[o] - (float)m * a;
}

// ---------------- apply norm+lrelu to pooled values, write concat features ----------------
__global__ void apply_kernel(int O, int outOff) {
    int i = blockIdx.x * blockDim.x + threadIdx.x;
    if (i >= BB*NN*O) return;
    int o  = i % O;
    int bn = i / O;
    float a = g_A[o], c = g_Cc[o];
    float sel = (a >= 0.f) ? g_YMAX[i] : g_YMIN[i];
    float v = fmaf(a, sel, c);
    g_FEAT[(size_t)bn*512 + outOff + o] = (v >= 0.f) ? v : 0.2f*v;
}

// ---------------- final 512x512 1x1 conv: 64x64 tiles + stats + transposed store ----------------
__global__ void gemm5_kernel(const float* __restrict__ w5) {
    constexpr int TC = 32;
    __shared__ float As[64][TC+1];
    __shared__ float Bs[64][TC+1];
    __shared__ float Ts[64][65];
    int r0 = blockIdx.x * 64;   // bn
    int o0 = blockIdx.y * 64;   // out channel
    int tx = threadIdx.x & 15, ty = threadIdx.x >> 4;
    float acc[4][4];
    #pragma unroll
    for (int i = 0; i < 4; i++)
        #pragma unroll
        for (int j = 0; j < 4; j++) acc[i][j] = 0.f;

    for (int c0 = 0; c0 < 512; c0 += TC) {
        for (int i = threadIdx.x; i < 64*TC; i += 256) {
            int r = i / TC, c = i - r*TC;
            As[r][c] = g_FEAT[(size_t)(r0 + r)*512 + c0 + c];
            Bs[r][c] = w5[(size_t)(o0 + r)*512 + c0 + c];
        }
        __syncthreads();
        for (int c = 0; c < TC; c++) {
            float av[4], bv[4];
            #pragma unroll
            for (int i = 0; i < 4; i++) { av[i] = As[ty*4+i][c]; bv[i] = Bs[tx*4+i][c]; }
            #pragma unroll
            for (int i = 0; i < 4; i++)
                #pragma unroll
                for (int j = 0; j < 4; j++) acc[i][j] = fmaf(av[i], bv[j], acc[i][j]);
        }
        __syncthreads();
    }

    // stats
    #pragma unroll
    for (int j = 0; j < 4; j++) {
        float s = 0.f, s2 = 0.f;
        #pragma unroll
        for (int i = 0; i < 4; i++) { float y = acc[i][j]; s += y; s2 = fmaf(y, y, s2); }
        atomicAdd(&g_SUM[o0 + tx*4 + j],   (double)s);
        atomicAdd(&g_SUMSQ[o0 + tx*4 + j], (double)s2);
    }

    // transpose through smem, coalesced store to (b, o, n)
    #pragma unroll
    for (int i = 0; i < 4; i++)
        #pragma unroll
        for (int j = 0; j < 4; j++) Ts[ty*4 + i][tx*4 + j] = acc[i][j];
    __syncthreads();
    int b = r0 >> 10, nb = r0 & 1023;
    int nl = threadIdx.x & 63;             // n within tile
    int oq = threadIdx.x >> 6;             // 0..3
    for (int ol = oq; ol < 64; ol += 4) {
        g_Y5[((size_t)b*512 + o0 + ol)*NN + nb + nl] = Ts[nl][ol];
    }
}

// ---------------- per (b,o) max/min over n ----------------
__global__ void reduce5_kernel() {
    __shared__ float smx[8], smn[8];
    int row = blockIdx.x;
    const float* p = g_Y5 + (size_t)row * NN;
    float mx = -FLT_MAX, mn = FLT_MAX;
    for (int i = threadIdx.x; i < NN; i += 256) {
        float v = p[i];
        mx = fmaxf(mx, v); mn = fminf(mn, v);
    }
    for (int s = 16; s; s >>= 1) {
        mx = fmaxf(mx, __shfl_down_sync(0xFFFFFFFFu, mx, s));
        mn = fminf(mn, __shfl_down_sync(0xFFFFFFFFu, mn, s));
    }
    if ((threadIdx.x & 31) == 0) { smx[threadIdx.x >> 5] = mx; smn[threadIdx.x >> 5] = mn; }
    __syncthreads();
    if (threadIdx.x == 0) {
        float M = smx[0], m_ = smn[0];
        for (int w = 1; w < 8; w++) { M = fmaxf(M, smx[w]); m_ = fminf(m_, smn[w]); }
        g_MX[row] = M; g_MN[row] = m_;
    }
}

// ---------------- final norm + global max + embedding ----------------
__global__ void emb_kernel(const float* __restrict__ wemb, float* __restrict__ out) {
    __shared__ float feat[512];
    int b = blockIdx.x, t = threadIdx.x;
    for (int o = t; o < 512; o += 256) {
        float a = g_A[o], c = g_Cc[o];
        float sel = (a >= 0.f) ? g_MX[b*512 + o] : g_MN[b*512 + o];
        float v = fmaf(a, sel, c);
        feat[o] = (v >= 0.f) ? v : 0.2f*v;
    }
    __syncthreads();
    const float* wr = wemb + (size_t)t * 512;
    float s = 0.f;
    for (int c = 0; c < 512; c++) s = fmaf(wr[c], feat[c], s);
    out[b*256 + t] = s;
}

// ---------------- host orchestration ----------------
template<int C, int O>
static void run_edge(const float* X, int ld, int off, const float* wcat,
                     const float* g, const float* beta, int outOff) {
    sq_kernel<C><<<(BB*NN + 255)/256, 256>>>(X, ld, off);
    dim3 gg(NN/64, NN/64, BB);
    gram_kernel<C><<<gg, 256>>>(X, ld, off);
    topk_kernel<<<BB*NN/8, 256>>>();
    dim3 zg(BB*NN/64, (2*O)/64);
    zgemm_kernel<C, 2*O><<<zg, 256>>>(X, ld, off, wcat);
    zero_stats_kernel<<<1, 512>>>();
    gather_kernel<O><<<BB*NN/8, 256>>>();
    stats_kernel<<<1, 512>>>(g, beta, (float)(BB*NN*KNN), O);
    apply_kernel<<<(BB*NN*O + 255)/256, 256>>>(O, outOff);
}

extern "C" void kernel_launch(void* const* d_in, const int* in_sizes, int n_in,
                              void* d_out, int out_size) {
    (void)in_sizes; (void)n_in; (void)out_size;
    const float* x    = (const float*)d_in[0];
    const float* w1   = (const float*)d_in[1];
    const float* g1   = (const float*)d_in[2];
    const float* b1   = (const float*)d_in[3];
    const float* w2   = (const float*)d_in[4];
    const float* g2   = (const float*)d_in[5];
    const float* b2   = (const float*)d_in[6];
    const float* w3   = (const float*)d_in[7];
    const float* g3   = (const float*)d_in[8];
    const float* b3   = (const float*)d_in[9];
    const float* w4   = (const float*)d_in[10];
    const float* g4   = (const float*)d_in[11];
    const float* b4   = (const float*)d_in[12];
    const float* w5   = (const float*)d_in[13];
    const float* g5   = (const float*)d_in[14];
    const float* b5   = (const float*)d_in[15];
    const float* wemb = (const float*)d_in[16];
    float* out = (float*)d_out;

    float *feat, *wcat;
    cudaGetSymbolAddress((void**)&feat, g_FEAT);
    cudaGetSymbolAddress((void**)&wcat, g_WCAT);

    prep_kernel<<<(90496 + 255)/256, 256>>>(w1, w2, w3, w4);

    run_edge<3,   64 >(x,    3,   0,   wcat + 0,     g1, b1, 0);
    run_edge<64,  64 >(feat, 512, 0,   wcat + 384,   g2, b2, 64);
    run_edge<64,  128>(feat, 512, 64,  wcat + 8576,  g3, b3, 128);
    run_edge<128, 256>(feat, 512, 128, wcat + 24960, g4, b4, 256);

    zero_stats_kernel<<<1, 512>>>();
    dim3 g5g(BB*NN/64, 512/64);
    gemm5_kernel<<<g5g, 256>>>(w5);
    reduce5_kernel<<<BB*512, 256>>>();
    stats_kernel<<<1, 512>>>(g5, b5, (float)(BB*NN), 512);
    emb_kernel<<<BB, 256>>>(wemb, out);
}

// round 3
// speedup vs baseline: 2.8584x; 1.4573x over previous
#include <cuda_runtime.h>
#include <math.h>
#include <float.h>

#define BB 8
#define NN 1024
#define KNN 20

// ---------------- static device scratch ----------------
__device__ float    g_G[(size_t)BB*NN*NN];        // pairwise 2*dot - sq[m]
__device__ float    g_SQ[BB*NN];
__device__ int      g_IDX[BB*NN*KNN];
__device__ float    g_Z2[(size_t)BB*NN*512];      // [bn][2O]: Zn | Zc
__device__ float    g_FEAT[(size_t)BB*NN*512];    // concat features (bn, c)
__device__ float    g_YMAX[(size_t)BB*NN*256];
__device__ float    g_YMIN[(size_t)BB*NN*256];
__device__ double   g_SUM[512];
__device__ double   g_SUMSQ[512];
__device__ float    g_A[512];
__device__ float    g_Cc[512];
__device__ float    g_WCAT[90496];                // [Wn ; Wc-Wn] per block
__device__ unsigned g_MXU[BB*512];                // encoded per-(b,o) max over n
__device__ unsigned g_MNU[BB*512];

__device__ __forceinline__ unsigned encf(float f) {
    unsigned b = __float_as_uint(f);
    return (b & 0x80000000u) ? ~b : (b | 0x80000000u);
}
__device__ __forceinline__ float decf(unsigned u) {
    return __uint_as_float((u & 0x80000000u) ? (u & 0x7FFFFFFFu) : ~u);
}

// WCAT offsets: b1:0 (128x3), b2:384 (128x64), b3:8576 (256x64), b4:24960 (512x128)
__global__ void prep_kernel(const float* __restrict__ w1, const float* __restrict__ w2,
                            const float* __restrict__ w3, const float* __restrict__ w4) {
    int t = blockIdx.x * blockDim.x + threadIdx.x;
    if (t < 384) {
        int r = t/3, c = t%3;
        g_WCAT[t] = (r < 64) ? w1[r*6 + c] : (w1[(r-64)*6 + 3 + c] - w1[(r-64)*6 + c]);
        return;
    }
    int u = t - 384;
    if (u < 8192) {
        int r = u/64, c = u%64;
        g_WCAT[384 + u] = (r < 64) ? w2[r*128 + c] : (w2[(r-64)*128 + 64 + c] - w2[(r-64)*128 + c]);
        return;
    }
    u -= 8192;
    if (u < 16384) {
        int r = u/64, c = u%64;
        g_WCAT[8576 + u] = (r < 128) ? w3[r*128 + c] : (w3[(r-128)*128 + 64 + c] - w3[(r-128)*128 + c]);
        return;
    }
    u -= 16384;
    if (u < 65536) {
        int r = u/128, c = u%128;
        g_WCAT[24960 + u] = (r < 256) ? w4[r*256 + c] : (w4[(r-256)*256 + 128 + c] - w4[(r-256)*256 + c]);
        return;
    }
}

template<int C>
__global__ void sq_kernel(const float* __restrict__ X, int ld, int off) {
    int i = blockIdx.x * blockDim.x + threadIdx.x;
    if (i >= BB*NN) return;
    const float* p = X + (size_t)i*ld + off;
    float s = 0.f;
    #pragma unroll
    for (int c = 0; c < C; c++) s = fmaf(p[c], p[c], s);
    g_SQ[i] = s;
}

// =======================================================================
// 128x128x16 SGEMM (NT): out[r][c] = sum_k A[r][k]*B[c][k]
// EPI 0: GRAM  -> g_G[(row)*1024 + colLocal] = 2*acc - sq
// EPI 1: PLAIN -> g_Z2[row*N2 + col]
// EPI 2: GEMM5 -> fused channel stats + per-(b,o) max/min (no Y store)
// =======================================================================
template<int EPI>
__global__ void __launch_bounds__(256, 2)
sgemm128(const float* __restrict__ A, int lda,
         const float* __restrict__ B, int ldb,
         int K, int N2) {
    __shared__ __align__(16) float sAs[16][132];
    __shared__ __align__(16) float sBs[16][132];

    int t  = threadIdx.x;
    int tx = t & 15, ty = t >> 4;
    int bz = blockIdx.z;
    int arow0 = bz*1024 + blockIdx.x*128;
    int brow0 = ((EPI == 0) ? bz*1024 : 0) + blockIdx.y*128;
    int n0    = blockIdx.y*128;

    const float* Abase = A + (size_t)arow0 * lda;
    const float* Bbase = B + (size_t)brow0 * ldb;

    float acc[8][8];
    #pragma unroll
    for (int i = 0; i < 8; i++)
        #pragma unroll
        for (int j = 0; j < 8; j++) acc[i][j] = 0.f;

    for (int kt = 0; kt < K; kt += 16) {
        #pragma unroll
        for (int rr = 0; rr < 2; rr++) {
            int f = t + rr*256;
            int row = f >> 2, q = f & 3;
            float4 va = *(const float4*)(Abase + (size_t)row*lda + kt + q*4);
            float4 vb = *(const float4*)(Bbase + (size_t)row*ldb + kt + q*4);
            sAs[q*4+0][row] = va.x; sAs[q*4+1][row] = va.y;
            sAs[q*4+2][row] = va.z; sAs[q*4+3][row] = va.w;
            sBs[q*4+0][row] = vb.x; sBs[q*4+1][row] = vb.y;
            sBs[q*4+2][row] = vb.z; sBs[q*4+3][row] = vb.w;
        }
        __syncthreads();
        #pragma unroll
        for (int k = 0; k < 16; k++) {
            float4 a0 = *(const float4*)&sAs[k][ty*8];
            float4 a1 = *(const float4*)&sAs[k][ty*8 + 4];
            float4 b0 = *(const float4*)&sBs[k][tx*8];
            float4 b1 = *(const float4*)&sBs[k][tx*8 + 4];
            float av[8] = {a0.x, a0.y, a0.z, a0.w, a1.x, a1.y, a1.z, a1.w};
            float bv[8] = {b0.x, b0.y, b0.z, b0.w, b1.x, b1.y, b1.z, b1.w};
            #pragma unroll
            for (int i = 0; i < 8; i++)
                #pragma unroll
                for (int j = 0; j < 8; j++) acc[i][j] = fmaf(av[i], bv[j], acc[i][j]);
        }
        __syncthreads();
    }

    if (EPI == 0) {
        int colb = n0 + tx*8;
        float sq[8];
        #pragma unroll
        for (int j = 0; j < 8; j++) sq[j] = g_SQ[bz*1024 + colb + j];
        #pragma unroll
        for (int i = 0; i < 8; i++) {
            size_t base = (size_t)(arow0 + ty*8 + i)*1024 + colb;
            float4 o0, o1;
            o0.x = 2.f*acc[i][0]-sq[0]; o0.y = 2.f*acc[i][1]-sq[1];
            o0.z = 2.f*acc[i][2]-sq[2]; o0.w = 2.f*acc[i][3]-sq[3];
            o1.x = 2.f*acc[i][4]-sq[4]; o1.y = 2.f*acc[i][5]-sq[5];
            o1.z = 2.f*acc[i][6]-sq[6]; o1.w = 2.f*acc[i][7]-sq[7];
            *(float4*)&g_G[base]   = o0;
            *(float4*)&g_G[base+4] = o1;
        }
    } else if (EPI == 1) {
        #pragma unroll
        for (int i = 0; i < 8; i++) {
            size_t base = (size_t)(arow0 + ty*8 + i)*N2 + n0 + tx*8;
            float4 o0 = {acc[i][0], acc[i][1], acc[i][2], acc[i][3]};
            float4 o1 = {acc[i][4], acc[i][5], acc[i][6], acc[i][7]};
            *(float4*)&g_Z2[base]   = o0;
            *(float4*)&g_Z2[base+4] = o1;
        }
    } else {
        double*   ssum = reinterpret_cast<double*>(&sAs[0][0]);
        double*   ssq  = ssum + 128;
        unsigned* smx  = reinterpret_cast<unsigned*>(ssq + 128);
        unsigned* smn  = smx + 128;
        if (t < 128) { ssum[t] = 0.0; ssq[t] = 0.0; smx[t] = 0u; smn[t] = 0xFFFFFFFFu; }
        __syncthreads();
        #pragma unroll
        for (int j = 0; j < 8; j++) {
            float s = 0.f, s2 = 0.f, mx = -FLT_MAX, mn = FLT_MAX;
            #pragma unroll
            for (int i = 0; i < 8; i++) {
                float y = acc[i][j];
                s += y; s2 = fmaf(y, y, s2);
                mx = fmaxf(mx, y); mn = fminf(mn, y);
            }
            int col = tx*8 + j;
            atomicAdd(&ssum[col], (double)s);
            atomicAdd(&ssq[col],  (double)s2);
            atomicMax(&smx[col], encf(mx));
            atomicMin(&smn[col], encf(mn));
        }
        __syncthreads();
        if (t < 128) {
            int o = n0 + t;
            int b = arow0 >> 10;
            atomicAdd(&g_SUM[o],   ssum[t]);
            atomicAdd(&g_SUMSQ[o], ssq[t]);
            atomicMax(&g_MXU[b*512 + o], smx[t]);
            atomicMin(&g_MNU[b*512 + o], smn[t]);
        }
    }
}

// ---------------- stage-1 small kernels (C=3) ----------------
template<int C>
__global__ void gram_kernel(const float* __restrict__ X, int ld, int off) {
    constexpr int TC = (C < 32) ? C : 32;
    __shared__ float As[64][TC+1];
    __shared__ float Bs[64][TC+1];
    int b  = blockIdx.z;
    int m0 = blockIdx.x * 64, n0 = blockIdx.y * 64;
    int tx = threadIdx.x & 15, ty = threadIdx.x >> 4;
    float acc[4][4];
    #pragma unroll
    for (int i = 0; i < 4; i++)
        #pragma unroll
        for (int j = 0; j < 4; j++) acc[i][j] = 0.f;
    for (int c0 = 0; c0 < C; c0 += TC) {
        for (int i = threadIdx.x; i < 64*TC; i += 256) {
            int r = i / TC, c = i - r*TC;
            As[r][c] = X[(size_t)(b*NN + n0 + r)*ld + off + c0 + c];
            Bs[r][c] = X[(size_t)(b*NN + m0 + r)*ld + off + c0 + c];
        }
        __syncthreads();
        for (int c = 0; c < TC; c++) {
            float av[4], bv[4];
            #pragma unroll
            for (int i = 0; i < 4; i++) { av[i] = As[ty*4+i][c]; bv[i] = Bs[tx*4+i][c]; }
            #pragma unroll
            for (int i = 0; i < 4; i++)
                #pragma unroll
                for (int j = 0; j < 4; j++) acc[i][j] = fmaf(av[i], bv[j], acc[i][j]);
        }
        __syncthreads();
    }
    float sqv[4];
    #pragma unroll
    for (int j = 0; j < 4; j++) sqv[j] = g_SQ[b*NN + m0 + tx*4 + j];
    #pragma unroll
    for (int i = 0; i < 4; i++)
        #pragma unroll
        for (int j = 0; j < 4; j++)
            g_G[((size_t)(b*NN) + n0 + ty*4 + i)*NN + m0 + tx*4 + j] = 2.f*acc[i][j] - sqv[j];
}

template<int C, int N2>
__global__ void zgemm_kernel(const float* __restrict__ X, int ld, int off,
                             const float* __restrict__ W) {
    constexpr int TC = (C < 32) ? C : 32;
    __shared__ float As[64][TC+1];
    __shared__ float Bs[64][TC+1];
    int r0 = blockIdx.x * 64;
    int o0 = blockIdx.y * 64;
    int tx = threadIdx.x & 15, ty = threadIdx.x >> 4;
    float acc[4][4];
    #pragma unroll
    for (int i = 0; i < 4; i++)
        #pragma unroll
        for (int j = 0; j < 4; j++) acc[i][j] = 0.f;
    for (int c0 = 0; c0 < C; c0 += TC) {
        for (int i = threadIdx.x; i < 64*TC; i += 256) {
            int r = i / TC, c = i - r*TC;
            As[r][c] = X[(size_t)(r0 + r)*ld + off + c0 + c];
            Bs[r][c] = W[(size_t)(o0 + r)*C + c0 + c];
        }
        __syncthreads();
        for (int c = 0; c < TC; c++) {
            float av[4], bv[4];
            #pragma unroll
            for (int i = 0; i < 4; i++) { av[i] = As[ty*4+i][c]; bv[i] = Bs[tx*4+i][c]; }
            #pragma unroll
            for (int i = 0; i < 4; i++)
                #pragma unroll
                for (int j = 0; j < 4; j++) acc[i][j] = fmaf(av[i], bv[j], acc[i][j]);
        }
        __syncthreads();
    }
    #pragma unroll
    for (int i = 0; i < 4; i++)
        #pragma unroll
        for (int j = 0; j < 4; j++)
            g_Z2[(size_t)(r0 + ty*4 + i)*N2 + o0 + tx*4 + j] = acc[i][j];
}

// ---------------- top-20: warp per row, lazy per-lane top-2 ----------------
__global__ void topk_kernel() {
    int warp = (blockIdx.x << 3) + (threadIdx.x >> 5);
    int l = threadIdx.x & 31;
    const float* grow = g_G + (size_t)warp * NN;
    float v[32];
    #pragma unroll
    for (int s = 0; s < 32; s++) v[s] = grow[s*32 + l];

    float m1 = -FLT_MAX, m2 = -FLT_MAX;
    int s1 = 0, s2 = 0;
    #pragma unroll
    for (int s = 0; s < 32; s++) {
        float x = v[s];
        if (x > m2) {
            if (x > m1) { m2 = m1; s2 = s1; m1 = x; s1 = s; }
            else        { m2 = x;  s2 = s; }
        }
    }
    bool dirty = false;

    for (int j = 0; j < KNN; j++) {
        float bv = m1;
        int   bm = (s1 << 5) | l;
        #pragma unroll
        for (int o = 16; o; o >>= 1) {
            float ov = __shfl_xor_sync(0xFFFFFFFFu, bv, o);
            int   om = __shfl_xor_sync(0xFFFFFFFFu, bm, o);
            if (ov > bv || (ov == bv && om < bm)) { bv = ov; bm = om; }
        }
        if (l == 0) g_IDX[warp*KNN + j] = bm;
        if ((bm & 31) == l) {
            #pragma unroll
            for (int s = 0; s < 32; s++) if (s == s1) v[s] = -FLT_MAX;
            if (!dirty) { m1 = m2; s1 = s2; dirty = true; }
            else {
                m1 = -FLT_MAX; m2 = -FLT_MAX; s1 = 0; s2 = 0;
                #pragma unroll
                for (int s = 0; s < 32; s++) {
                    float x = v[s];
                    if (x > m2) {
                        if (x > m1) { m2 = m1; s2 = s1; m1 = x; s1 = s; }
                        else        { m2 = x;  s2 = s; }
                    }
                }
                dirty = false;
            }
        }
    }
}

__global__ void zero_stats_kernel() {
    int o = threadIdx.x;
    if (o < 512) { g_SUM[o] = 0.0; g_SUMSQ[o] = 0.0; }
}

__global__ void init5_kernel() {
    int t = blockIdx.x * blockDim.x + threadIdx.x;
    if (t < 512) { g_SUM[t] = 0.0; g_SUMSQ[t] = 0.0; }
    if (t < BB*512) { g_MXU[t] = 0u; g_MNU[t] = 0xFFFFFFFFu; }
}

// ---------------- gather + k-reduce ----------------
template<int O>
__global__ void gather_kernel() {
    constexpr int PL = 256 / O;
    __shared__ int sidx[8*KNN];
    int n0 = blockIdx.x * 8;
    int b  = n0 >> 10;
    int t  = threadIdx.x;
    for (int i = t; i < 8*KNN; i += 256) sidx[i] = g_IDX[n0*KNN + i];
    __syncthreads();

    int ch = t & (O - 1);
    int pl = t / O;
    const float* Zb = g_Z2 + ((size_t)b << 10) * (2*O);
    float S = 0.f, S2 = 0.f;
    for (int p = pl; p < 8; p += PL) {
        int n = n0 + p;
        float ctr = g_Z2[(size_t)n*(2*O) + O + ch];
        float mx = -FLT_MAX, mn = FLT_MAX, sz = 0.f, sz2 = 0.f;
        #pragma unroll
        for (int j = 0; j < KNN; j++) {
            int m = sidx[p*KNN + j];
            float z = Zb[(size_t)m*(2*O) + ch];
            mx = fmaxf(mx, z); mn = fminf(mn, z);
            sz += z; sz2 = fmaf(z, z, sz2);
        }
        g_YMAX[(size_t)n*O + ch] = mx + ctr;
        g_YMIN[(size_t)n*O + ch] = mn + ctr;
        S  += sz + (float)KNN * ctr;
        S2 += sz2 + 2.f*ctr*sz + (float)KNN * ctr * ctr;
    }
    atomicAdd(&g_SUM[ch],   (double)S);
    atomicAdd(&g_SUMSQ[ch], (double)S2);
}

__global__ void stats_kernel(const float* __restrict__ g, const float* __restrict__ beta,
                             float count, int O) {
    int o = threadIdx.x;
    if (o >= O) return;
    double m   = g_SUM[o]   / (double)count;
    double var = g_SUMSQ[o] / (double)count - m*m;
    float a = g[o] / sqrtf((float)var + 1e-5f);
    g_A[o]  = a;
    g_Cc[o] = beta[o] - (float)m * a;
}

__global__ void apply_kernel(int O, int outOff) {
    int i = blockIdx.x * blockDim.x + threadIdx.x;
    if (i >= BB*NN*O) return;
    int o  = i % O;
    int bn = i / O;
    float a = g_A[o], c = g_Cc[o];
    float sel = (a >= 0.f) ? g_YMAX[i] : g_YMIN[i];
    float v = fmaf(a, sel, c);
    g_FEAT[(size_t)bn*512 + outOff + o] = (v >= 0.f) ? v : 0.2f*v;
}

// ---------------- final norm + global max + embedding ----------------
__global__ void emb_kernel(const float* __restrict__ wemb, float* __restrict__ out) {
    __shared__ float feat[512];
    int b = blockIdx.x, t = threadIdx.x;
    for (int o = t; o < 512; o += 256) {
        float a = g_A[o], c = g_Cc[o];
        float sel = (a >= 0.f) ? decf(g_MXU[b*512 + o]) : decf(g_MNU[b*512 + o]);
        float v = fmaf(a, sel, c);
        feat[o] = (v >= 0.f) ? v : 0.2f*v;
    }
    __syncthreads();
    const float* wr = wemb + (size_t)t * 512;
    float s = 0.f;
    for (int c = 0; c < 512; c++) s = fmaf(wr[c], feat[c], s);
    out[b*256 + t] = s;
}

// ---------------- host orchestration ----------------
template<int C, int O>
static void run_edge_big(const float* feat, int off, const float* wcat,
                         const float* g, const float* beta, int outOff) {
    sq_kernel<C><<<32, 256>>>(feat, 512, off);
    dim3 gg(8, 8, BB);
    sgemm128<0><<<gg, 256>>>(feat + off, 512, feat + off, 512, C, 0);
    topk_kernel<<<BB*NN/8, 256>>>();
    dim3 zg(64, (2*O)/128, 1);
    sgemm128<1><<<zg, 256>>>(feat + off, 512, wcat, C, C, 2*O);
    zero_stats_kernel<<<1, 512>>>();
    gather_kernel<O><<<BB*NN/8, 256>>>();
    stats_kernel<<<1, 512>>>(g, beta, (float)(BB*NN*KNN), O);
    apply_kernel<<<(BB*NN*O + 255)/256, 256>>>(O, outOff);
}

extern "C" void kernel_launch(void* const* d_in, const int* in_sizes, int n_in,
                              void* d_out, int out_size) {
    (void)in_sizes; (void)n_in; (void)out_size;
    const float* x    = (const float*)d_in[0];
    const float* w1   = (const float*)d_in[1];
    const float* g1   = (const float*)d_in[2];
    const float* b1   = (const float*)d_in[3];
    const float* w2   = (const float*)d_in[4];
    const float* g2   = (const float*)d_in[5];
    const float* b2   = (const float*)d_in[6];
    const float* w3   = (const float*)d_in[7];
    const float* g3   = (const float*)d_in[8];
    const float* b3   = (const float*)d_in[9];
    const float* w4   = (const float*)d_in[10];
    const float* g4   = (const float*)d_in[11];
    const float* b4   = (const float*)d_in[12];
    const float* w5   = (const float*)d_in[13];
    const float* g5   = (const float*)d_in[14];
    const float* b5   = (const float*)d_in[15];
    const float* wemb = (const float*)d_in[16];
    float* out = (float*)d_out;

    float *feat, *wcat;
    cudaGetSymbolAddress((void**)&feat, g_FEAT);
    cudaGetSymbolAddress((void**)&wcat, g_WCAT);

    prep_kernel<<<(90496 + 255)/256, 256>>>(w1, w2, w3, w4);

    // ---- stage 1 (C=3): small-K path ----
    sq_kernel<3><<<32, 256>>>(x, 3, 0);
    dim3 gg1(NN/64, NN/64, BB);
    gram_kernel<3><<<gg1, 256>>>(x, 3, 0);
    topk_kernel<<<BB*NN/8, 256>>>();
    dim3 zg1(BB*NN/64, 2);
    zgemm_kernel<3, 128><<<zg1, 256>>>(x, 3, 0, wcat);
    zero_stats_kernel<<<1, 512>>>();
    gather_kernel<64><<<BB*NN/8, 256>>>();
    stats_kernel<<<1, 512>>>(g1, b1, (float)(BB*NN*KNN), 64);
    apply_kernel<<<(BB*NN*64 + 255)/256, 256>>>(64, 0);

    // ---- stages 2-4: fast SGEMM path ----
    run_edge_big<64,  64 >(feat, 0,   wcat + 384,   g2, b2, 64);
    run_edge_big<64,  128>(feat, 64,  wcat + 8576,  g3, b3, 128);
    run_edge_big<128, 256>(feat, 128, wcat + 24960, g4, b4, 256);

    // ---- final conv 512x512 fused with stats + max/min ----
    init5_kernel<<<8, 512>>>();
    dim3 g5g(64, 4, 1);
    sgemm128<2><<<g5g, 256>>>(feat, 512, w5, 512, 512, 0);
    stats_kernel<<<1, 512>>>(g5, b5, (float)(BB*NN), 512);
    emb_kernel<<<BB, 256>>>(wemb, out);
}

// round 4
// speedup vs baseline: 3.1472x; 1.1010x over previous
#include <cuda_runtime.h>
#include <math.h>
#include <float.h>

#define BB 8
#define NN 1024
#define KNN 20

// ---------------- static device scratch ----------------
__device__ float    g_G[(size_t)BB*NN*NN];        // pairwise 2*dot - sq[m]
__device__ float    g_SQ[BB*NN];
__device__ int      g_IDX[BB*NN*KNN];
__device__ float    g_Z2[(size_t)BB*NN*512];      // [bn][2O]: Zn | Zc
__device__ float    g_FEAT[(size_t)BB*NN*512];    // concat features (bn, c)
__device__ float    g_YMAX[(size_t)BB*NN*256];
__device__ float    g_YMIN[(size_t)BB*NN*256];
__device__ double   g_SUM[512];
__device__ double   g_SUMSQ[512];
__device__ float    g_A[512];
__device__ float    g_Cc[512];
__device__ float    g_WCAT[90496];                // [Wn ; Wc-Wn] per block
__device__ unsigned g_MXU[BB*512];
__device__ unsigned g_MNU[BB*512];

__device__ __forceinline__ unsigned encf(float f) {
    unsigned b = __float_as_uint(f);
    return (b & 0x80000000u) ? ~b : (b | 0x80000000u);
}
__device__ __forceinline__ float decf(unsigned u) {
    return __uint_as_float((u & 0x80000000u) ? (u & 0x7FFFFFFFu) : ~u);
}

// WCAT offsets: b1:0 (128x3), b2:384 (128x64), b3:8576 (256x64), b4:24960 (512x128)
__global__ void prep_kernel(const float* __restrict__ w1, const float* __restrict__ w2,
                            const float* __restrict__ w3, const float* __restrict__ w4) {
    int t = blockIdx.x * blockDim.x + threadIdx.x;
    if (t < 384) {
        int r = t/3, c = t%3;
        g_WCAT[t] = (r < 64) ? w1[r*6 + c] : (w1[(r-64)*6 + 3 + c] - w1[(r-64)*6 + c]);
        return;
    }
    int u = t - 384;
    if (u < 8192) {
        int r = u/64, c = u%64;
        g_WCAT[384 + u] = (r < 64) ? w2[r*128 + c] : (w2[(r-64)*128 + 64 + c] - w2[(r-64)*128 + c]);
        return;
    }
    u -= 8192;
    if (u < 16384) {
        int r = u/64, c = u%64;
        g_WCAT[8576 + u] = (r < 128) ? w3[r*128 + c] : (w3[(r-128)*128 + 64 + c] - w3[(r-128)*128 + c]);
        return;
    }
    u -= 16384;
    if (u < 65536) {
        int r = u/128, c = u%128;
        g_WCAT[24960 + u] = (r < 256) ? w4[r*256 + c] : (w4[(r-256)*256 + 128 + c] - w4[(r-256)*256 + c]);
        return;
    }
}

template<int C>
__global__ void sq_kernel(const float* __restrict__ X, int ld, int off) {
    int i = blockIdx.x * blockDim.x + threadIdx.x;
    if (i >= BB*NN) return;
    const float* p = X + (size_t)i*ld + off;
    float s = 0.f;
    #pragma unroll
    for (int c = 0; c < C; c++) s = fmaf(p[c], p[c], s);
    g_SQ[i] = s;
}

// =======================================================================
// Symmetric gram: one block per (i<=j) 128x128 tile pair per batch.
// Direct store: G[n][m] = 2*acc - sq[m]; transposed (i!=j): G[m][n] = 2*acc - sq[n]
// =======================================================================
__global__ void __launch_bounds__(256, 2)
gram_sym(const float* __restrict__ A, int lda, int K) {
    __shared__ __align__(16) float sAs[16][132];
    __shared__ __align__(16) float sBs[16][132];

    int t  = threadIdx.x;
    int tx = t & 15, ty = t >> 4;
    int bz = blockIdx.z;

    int idx = blockIdx.x;
    int ib = 0;
    while (idx >= 8 - ib) { idx -= 8 - ib; ib++; }
    int jb = ib + idx;

    int arow0 = ib * 128;          // local within batch
    int brow0 = jb * 128;
    const float* Abase = A + (size_t)(bz*1024 + arow0) * lda;
    const float* Bbase = A + (size_t)(bz*1024 + brow0) * lda;

    float acc[8][8];
    #pragma unroll
    for (int i = 0; i < 8; i++)
        #pragma unroll
        for (int j = 0; j < 8; j++) acc[i][j] = 0.f;

    for (int kt = 0; kt < K; kt += 16) {
        #pragma unroll
        for (int rr = 0; rr < 2; rr++) {
            int f = t + rr*256;
            int row = f >> 2, q = f & 3;
            float4 va = *(const float4*)(Abase + (size_t)row*lda + kt + q*4);
            float4 vb = *(const float4*)(Bbase + (size_t)row*lda + kt + q*4);
            sAs[q*4+0][row] = va.x; sAs[q*4+1][row] = va.y;
            sAs[q*4+2][row] = va.z; sAs[q*4+3][row] = va.w;
            sBs[q*4+0][row] = vb.x; sBs[q*4+1][row] = vb.y;
            sBs[q*4+2][row] = vb.z; sBs[q*4+3][row] = vb.w;
        }
        __syncthreads();
        #pragma unroll
        for (int k = 0; k < 16; k++) {
            float4 a0 = *(const float4*)&sAs[k][ty*8];
            float4 a1 = *(const float4*)&sAs[k][ty*8 + 4];
            float4 b0 = *(const float4*)&sBs[k][tx*8];
            float4 b1 = *(const float4*)&sBs[k][tx*8 + 4];
            float av[8] = {a0.x, a0.y, a0.z, a0.w, a1.x, a1.y, a1.z, a1.w};
            float bv[8] = {b0.x, b0.y, b0.z, b0.w, b1.x, b1.y, b1.z, b1.w};
            #pragma unroll
            for (int i = 0; i < 8; i++)
                #pragma unroll
                for (int j = 0; j < 8; j++) acc[i][j] = fmaf(av[i], bv[j], acc[i][j]);
        }
        __syncthreads();
    }

    float sqa[8], sqb[8];
    #pragma unroll
    for (int i = 0; i < 8; i++) sqa[i] = g_SQ[bz*1024 + arow0 + ty*8 + i];
    #pragma unroll
    for (int j = 0; j < 8; j++) sqb[j] = g_SQ[bz*1024 + brow0 + tx*8 + j];

    // direct tile
    #pragma unroll
    for (int i = 0; i < 8; i++) {
        size_t base = (size_t)(bz*1024 + arow0 + ty*8 + i)*1024 + brow0 + tx*8;
        float4 o0, o1;
        o0.x = 2.f*acc[i][0]-sqb[0]; o0.y = 2.f*acc[i][1]-sqb[1];
        o0.z = 2.f*acc[i][2]-sqb[2]; o0.w = 2.f*acc[i][3]-sqb[3];
        o1.x = 2.f*acc[i][4]-sqb[4]; o1.y = 2.f*acc[i][5]-sqb[5];
        o1.z = 2.f*acc[i][6]-sqb[6]; o1.w = 2.f*acc[i][7]-sqb[7];
        *(float4*)&g_G[base]   = o0;
        *(float4*)&g_G[base+4] = o1;
    }

    if (ib != jb) {
        // transposed tile via smem staging, 8 passes of 16 G-rows
        float (*tbuf)[132] = sAs;
        #pragma unroll
        for (int p = 0; p < 8; p++) {
            __syncthreads();
            #pragma unroll
            for (int i = 0; i < 8; i++)
                tbuf[tx][ty*8 + i] = 2.f*acc[i][p] - sqa[i];
            __syncthreads();
            int rowIdx = t >> 4;      // 0..15 -> tx value
            int seg    = t & 15;      // col segment of 8 floats
            size_t base = (size_t)(bz*1024 + brow0 + rowIdx*8 + p)*1024 + arow0 + seg*8;
            float4 o0 = {tbuf[rowIdx][seg*8+0], tbuf[rowIdx][seg*8+1],
                         tbuf[rowIdx][seg*8+2], tbuf[rowIdx][seg*8+3]};
            float4 o1 = {tbuf[rowIdx][seg*8+4], tbuf[rowIdx][seg*8+5],
                         tbuf[rowIdx][seg*8+6], tbuf[rowIdx][seg*8+7]};
            *(float4*)&g_G[base]   = o0;
            *(float4*)&g_G[base+4] = o1;
        }
    }
}

// =======================================================================
// 128x128x16 SGEMM (NT). EPI 1: plain store to g_Z2. EPI 2: gemm5 fused stats.
// =======================================================================
template<int EPI>
__global__ void __launch_bounds__(256, 2)
sgemm128(const float* __restrict__ A, int lda,
         const float* __restrict__ B, int ldb,
         int K, int N2) {
    __shared__ __align__(16) float sAs[16][132];
    __shared__ __align__(16) float sBs[16][132];

    int t  = threadIdx.x;
    int tx = t & 15, ty = t >> 4;
    int arow0 = blockIdx.x*128;
    int n0    = blockIdx.y*128;

    const float* Abase = A + (size_t)arow0 * lda;
    const float* Bbase = B + (size_t)n0 * ldb;

    float acc[8][8];
    #pragma unroll
    for (int i = 0; i < 8; i++)
        #pragma unroll
        for (int j = 0; j < 8; j++) acc[i][j] = 0.f;

    for (int kt = 0; kt < K; kt += 16) {
        #pragma unroll
        for (int rr = 0; rr < 2; rr++) {
            int f = t + rr*256;
            int row = f >> 2, q = f & 3;
            float4 va = *(const float4*)(Abase + (size_t)row*lda + kt + q*4);
            float4 vb = *(const float4*)(Bbase + (size_t)row*ldb + kt + q*4);
            sAs[q*4+0][row] = va.x; sAs[q*4+1][row] = va.y;
            sAs[q*4+2][row] = va.z; sAs[q*4+3][row] = va.w;
            sBs[q*4+0][row] = vb.x; sBs[q*4+1][row] = vb.y;
            sBs[q*4+2][row] = vb.z; sBs[q*4+3][row] = vb.w;
        }
        __syncthreads();
        #pragma unroll
        for (int k = 0; k < 16; k++) {
            float4 a0 = *(const float4*)&sAs[k][ty*8];
            float4 a1 = *(const float4*)&sAs[k][ty*8 + 4];
            float4 b0 = *(const float4*)&sBs[k][tx*8];
            float4 b1 = *(const float4*)&sBs[k][tx*8 + 4];
            float av[8] = {a0.x, a0.y, a0.z, a0.w, a1.x, a1.y, a1.z, a1.w};
            float bv[8] = {b0.x, b0.y, b0.z, b0.w, b1.x, b1.y, b1.z, b1.w};
            #pragma unroll
            for (int i = 0; i < 8; i++)
                #pragma unroll
                for (int j = 0; j < 8; j++) acc[i][j] = fmaf(av[i], bv[j], acc[i][j]);
        }
        __syncthreads();
    }

    if (EPI == 1) {
        #pragma unroll
        for (int i = 0; i < 8; i++) {
            size_t base = (size_t)(arow0 + ty*8 + i)*N2 + n0 + tx*8;
            float4 o0 = {acc[i][0], acc[i][1], acc[i][2], acc[i][3]};
            float4 o1 = {acc[i][4], acc[i][5], acc[i][6], acc[i][7]};
            *(float4*)&g_Z2[base]   = o0;
            *(float4*)&g_Z2[base+4] = o1;
        }
    } else {
        double*   ssum = reinterpret_cast<double*>(&sAs[0][0]);
        double*   ssq  = ssum + 128;
        unsigned* smx  = reinterpret_cast<unsigned*>(ssq + 128);
        unsigned* smn  = smx + 128;
        if (t < 128) { ssum[t] = 0.0; ssq[t] = 0.0; smx[t] = 0u; smn[t] = 0xFFFFFFFFu; }
        __syncthreads();
        #pragma unroll
        for (int j = 0; j < 8; j++) {
            float s = 0.f, s2 = 0.f, mx = -FLT_MAX, mn = FLT_MAX;
            #pragma unroll
            for (int i = 0; i < 8; i++) {
                float y = acc[i][j];
                s += y; s2 = fmaf(y, y, s2);
                mx = fmaxf(mx, y); mn = fminf(mn, y);
            }
            int col = tx*8 + j;
            atomicAdd(&ssum[col], (double)s);
            atomicAdd(&ssq[col],  (double)s2);
            atomicMax(&smx[col], encf(mx));
            atomicMin(&smn[col], encf(mn));
        }
        __syncthreads();
        if (t < 128) {
            int o = n0 + t;
            int b = arow0 >> 10;
            atomicAdd(&g_SUM[o],   ssum[t]);
            atomicAdd(&g_SUMSQ[o], ssq[t]);
            atomicMax(&g_MXU[b*512 + o], smx[t]);
            atomicMin(&g_MNU[b*512 + o], smn[t]);
        }
    }
}

// ---------------- stage-1 zgemm (C=3) ----------------
template<int C, int N2>
__global__ void zgemm_kernel(const float* __restrict__ X, int ld, int off,
                             const float* __restrict__ W) {
    constexpr int TC = (C < 32) ? C : 32;
    __shared__ float As[64][TC+1];
    __shared__ float Bs[64][TC+1];
    int r0 = blockIdx.x * 64;
    int o0 = blockIdx.y * 64;
    int tx = threadIdx.x & 15, ty = threadIdx.x >> 4;
    float acc[4][4];
    #pragma unroll
    for (int i = 0; i < 4; i++)
        #pragma unroll
        for (int j = 0; j < 4; j++) acc[i][j] = 0.f;
    for (int c0 = 0; c0 < C; c0 += TC) {
        for (int i = threadIdx.x; i < 64*TC; i += 256) {
            int r = i / TC, c = i - r*TC;
            As[r][c] = X[(size_t)(r0 + r)*ld + off + c0 + c];
            Bs[r][c] = W[(size_t)(o0 + r)*C + c0 + c];
        }
        __syncthreads();
        for (int c = 0; c < TC; c++) {
            float av[4], bv[4];
            #pragma unroll
            for (int i = 0; i < 4; i++) { av[i] = As[ty*4+i][c]; bv[i] = Bs[tx*4+i][c]; }
            #pragma unroll
            for (int i = 0; i < 4; i++)
                #pragma unroll
                for (int j = 0; j < 4; j++) acc[i][j] = fmaf(av[i], bv[j], acc[i][j]);
        }
        __syncthreads();
    }
    #pragma unroll
    for (int i = 0; i < 4; i++)
        #pragma unroll
        for (int j = 0; j < 4; j++)
            g_Z2[(size_t)(r0 + ty*4 + i)*N2 + o0 + tx*4 + j] = acc[i][j];
}

// ---------------- stage-1 fused distances + top-20 ----------------
__global__ void topk1_kernel(const float* __restrict__ x) {
    __shared__ float spx[1024], spy[1024], spz[1024], ssq[1024];
    int n0 = blockIdx.x * 8;              // global bn
    int b  = n0 >> 10;
    int t  = threadIdx.x;
    const float* xb = x + (size_t)b * 3072;
    for (int m = t; m < 1024; m += 256) {
        float px = xb[m*3], py = xb[m*3+1], pz = xb[m*3+2];
        spx[m] = px; spy[m] = py; spz[m] = pz;
        ssq[m] = fmaf(px, px, fmaf(py, py, pz*pz));
    }
    __syncthreads();

    int warp = t >> 5, l = t & 31;
    int ln = (n0 & 1023) + warp;          // local row
    float dnx = 2.f*spx[ln], dny = 2.f*spy[ln], dnz = 2.f*spz[ln];

    float v[32];
    #pragma unroll
    for (int s = 0; s < 32; s++) {
        int m = s*32 + l;
        v[s] = fmaf(dnx, spx[m], fmaf(dny, spy[m], fmaf(dnz, spz[m], -ssq[m])));
    }

    float m1 = -FLT_MAX, m2 = -FLT_MAX;
    int s1 = 0, s2 = 0;
    #pragma unroll
    for (int s = 0; s < 32; s++) {
        float xv = v[s];
        if (xv > m2) {
            if (xv > m1) { m2 = m1; s2 = s1; m1 = xv; s1 = s; }
            else         { m2 = xv; s2 = s; }
        }
    }
    bool dirty = false;
    int row = n0 + warp;
    for (int j = 0; j < KNN; j++) {
        float bv = m1;
        int   bm = (s1 << 5) | l;
        #pragma unroll
        for (int o = 16; o; o >>= 1) {
            float ov = __shfl_xor_sync(0xFFFFFFFFu, bv, o);
            int   om = __shfl_xor_sync(0xFFFFFFFFu, bm, o);
            if (ov > bv || (ov == bv && om < bm)) { bv = ov; bm = om; }
        }
        if (l == 0) g_IDX[row*KNN + j] = bm;
        if ((bm & 31) == l) {
            #pragma unroll
            for (int s = 0; s < 32; s++) if (s == s1) v[s] = -FLT_MAX;
            if (!dirty) { m1 = m2; s1 = s2; dirty = true; }
            else {
                m1 = -FLT_MAX; m2 = -FLT_MAX; s1 = 0; s2 = 0;
                #pragma unroll
                for (int s = 0; s < 32; s++) {
                    float xv = v[s];
                    if (xv > m2) {
                        if (xv > m1) { m2 = m1; s2 = s1; m1 = xv; s1 = s; }
                        else         { m2 = xv; s2 = s; }
                    }
                }
                dirty = false;
            }
        }
    }
}

// ---------------- top-20 from g_G (stages 2-4) ----------------
__global__ void topk_kernel() {
    int warp = (blockIdx.x << 3) + (threadIdx.x >> 5);
    int l = threadIdx.x & 31;
    const float* grow = g_G + (size_t)warp * NN;
    float v[32];
    #pragma unroll
    for (int s = 0; s < 32; s++) v[s] = grow[s*32 + l];

    float m1 = -FLT_MAX, m2 = -FLT_MAX;
    int s1 = 0, s2 = 0;
    #pragma unroll
    for (int s = 0; s < 32; s++) {
        float x = v[s];
        if (x > m2) {
            if (x > m1) { m2 = m1; s2 = s1; m1 = x; s1 = s; }
            else        { m2 = x;  s2 = s; }
        }
    }
    bool dirty = false;

    for (int j = 0; j < KNN; j++) {
        float bv = m1;
        int   bm = (s1 << 5) | l;
        #pragma unroll
        for (int o = 16; o; o >>= 1) {
            float ov = __shfl_xor_sync(0xFFFFFFFFu, bv, o);
            int   om = __shfl_xor_sync(0xFFFFFFFFu, bm, o);
            if (ov > bv || (ov == bv && om < bm)) { bv = ov; bm = om; }
        }
        if (l == 0) g_IDX[warp*KNN + j] = bm;
        if ((bm & 31) == l) {
            #pragma unroll
            for (int s = 0; s < 32; s++) if (s == s1) v[s] = -FLT_MAX;
            if (!dirty) { m1 = m2; s1 = s2; dirty = true; }
            else {
                m1 = -FLT_MAX; m2 = -FLT_MAX; s1 = 0; s2 = 0;
                #pragma unroll
                for (int s = 0; s < 32; s++) {
                    float x = v[s];
                    if (x > m2) {
                        if (x > m1) { m2 = m1; s2 = s1; m1 = x; s1 = s; }
                        else        { m2 = x;  s2 = s; }
                    }
                }
                dirty = false;
            }
        }
    }
}

// ---------------- gather + k-reduce ----------------
template<int O>
__global__ void gather_kernel() {
    constexpr int PL = 256 / O;
    __shared__ int sidx[8*KNN];
    int n0 = blockIdx.x * 8;
    int b  = n0 >> 10;
    int t  = threadIdx.x;
    for (int i = t; i < 8*KNN; i += 256) sidx[i] = g_IDX[n0*KNN + i];
    __syncthreads();

    int ch = t & (O - 1);
    int pl = t / O;
    const float* Zb = g_Z2 + ((size_t)b << 10) * (2*O);
    float S = 0.f, S2 = 0.f;
    for (int p = pl; p < 8; p += PL) {
        int n = n0 + p;
        float ctr = g_Z2[(size_t)n*(2*O) + O + ch];
        float mx = -FLT_MAX, mn = FLT_MAX, sz = 0.f, sz2 = 0.f;
        #pragma unroll
        for (int j = 0; j < KNN; j++) {
            int m = sidx[p*KNN + j];
            float z = Zb[(size_t)m*(2*O) + ch];
            mx = fmaxf(mx, z); mn = fminf(mn, z);
            sz += z; sz2 = fmaf(z, z, sz2);
        }
        g_YMAX[(size_t)n*O + ch] = mx + ctr;
        g_YMIN[(size_t)n*O + ch] = mn + ctr;
        S  += sz + (float)KNN * ctr;
        S2 += sz2 + 2.f*ctr*sz + (float)KNN * ctr * ctr;
    }
    atomicAdd(&g_SUM[ch],   (double)S);
    atomicAdd(&g_SUMSQ[ch], (double)S2);
}

// ---------------- BN affine coeffs; self-resets accumulators ----------------
__global__ void stats_kernel(const float* __restrict__ g, const float* __restrict__ beta,
                             float count, int O, int resetMM) {
    int o = threadIdx.x;
    if (resetMM) {
        for (int i = o; i < BB*512; i += 512) { g_MXU[i] = 0u; g_MNU[i] = 0xFFFFFFFFu; }
    }
    if (o >= O) return;
    double m   = g_SUM[o]   / (double)count;
    double var = g_SUMSQ[o] / (double)count - m*m;
    float a = g[o] / sqrtf((float)var + 1e-5f);
    g_A[o]  = a;
    g_Cc[o] = beta[o] - (float)m * a;
    g_SUM[o] = 0.0; g_SUMSQ[o] = 0.0;
}

__global__ void apply_kernel(int O, int outOff) {
    int i = blockIdx.x * blockDim.x + threadIdx.x;
    if (i >= BB*NN*O) return;
    int o  = i % O;
    int bn = i / O;
    float a = g_A[o], c = g_Cc[o];
    float sel = (a >= 0.f) ? g_YMAX[i] : g_YMIN[i];
    float v = fmaf(a, sel, c);
    g_FEAT[(size_t)bn*512 + outOff + o] = (v >= 0.f) ? v : 0.2f*v;
}

// ---------------- final norm + global max + embedding ----------------
__global__ void emb_kernel(const float* __restrict__ wemb, float* __restrict__ out) {
    __shared__ float feat[512];
    int b = blockIdx.x, t = threadIdx.x;
    for (int o = t; o < 512; o += 256) {
        float a = g_A[o], c = g_Cc[o];
        float sel = (a >= 0.f) ? decf(g_MXU[b*512 + o]) : decf(g_MNU[b*512 + o]);
        float v = fmaf(a, sel, c);
        feat[o] = (v >= 0.f) ? v : 0.2f*v;
    }
    __syncthreads();
    const float* wr = wemb + (size_t)t * 512;
    float s = 0.f;
    for (int c = 0; c < 512; c++) s = fmaf(wr[c], feat[c], s);
    out[b*256 + t] = s;
}

// ---------------- host orchestration ----------------
template<int C, int O>
static void run_edge_big(const float* feat, int off, const float* wcat,
                         const float* g, const float* beta, int outOff, int resetMM) {
    sq_kernel<C><<<32, 256>>>(feat, 512, off);
    dim3 gg(36, 1, BB);
    gram_sym<<<gg, 256>>>(feat + off, 512, C);
    topk_kernel<<<BB*NN/8, 256>>>();
    dim3 zg(64, (2*O)/128, 1);
    sgemm128<1><<<zg, 256>>>(feat + off, 512, wcat, C, C, 2*O);
    gather_kernel<O><<<BB*NN/8, 256>>>();
    stats_kernel<<<1, 512>>>(g, beta, (float)(BB*NN*KNN), O, resetMM);
    apply_kernel<<<(BB*NN*O + 255)/256, 256>>>(O, outOff);
}

extern "C" void kernel_launch(void* const* d_in, const int* in_sizes, int n_in,
                              void* d_out, int out_size) {
    (void)in_sizes; (void)n_in; (void)out_size;
    const float* x    = (const float*)d_in[0];
    const float* w1   = (const float*)d_in[1];
    const float* g1   = (const float*)d_in[2];
    const float* b1   = (const float*)d_in[3];
    const float* w2   = (const float*)d_in[4];
    const float* g2   = (const float*)d_in[5];
    const float* b2   = (const float*)d_in[6];
    const float* w3   = (const float*)d_in[7];
    const float* g3   = (const float*)d_in[8];
    const float* b3   = (const float*)d_in[9];
    const float* w4   = (const float*)d_in[10];
    const float* g4   = (const float*)d_in[11];
    const float* b4   = (const float*)d_in[12];
    const float* w5   = (const float*)d_in[13];
    const float* g5   = (const float*)d_in[14];
    const float* b5   = (const float*)d_in[15];
    const float* wemb = (const float*)d_in[16];
    float* out = (float*)d_out;

    float *feat, *wcat;
    cudaGetSymbolAddress((void**)&feat, g_FEAT);
    cudaGetSymbolAddress((void**)&wcat, g_WCAT);

    prep_kernel<<<(90496 + 255)/256, 256>>>(w1, w2, w3, w4);

    // ---- stage 1 (C=3): fused distance + topk, small zgemm ----
    topk1_kernel<<<BB*NN/8, 256>>>(x);
    dim3 zg1(BB*NN/64, 2);
    zgemm_kernel<3, 128><<<zg1, 256>>>(x, 3, 0, wcat);
    gather_kernel<64><<<BB*NN/8, 256>>>();
    stats_kernel<<<1, 512>>>(g1, b1, (float)(BB*NN*KNN), 64, 0);
    apply_kernel<<<(BB*NN*64 + 255)/256, 256>>>(64, 0);

    // ---- stages 2-4: symmetric gram + SGEMM path ----
    run_edge_big<64,  64 >(feat, 0,   wcat + 384,   g2, b2, 64, 0);
    run_edge_big<64,  128>(feat, 64,  wcat + 8576,  g3, b3, 128, 0);
    run_edge_big<128, 256>(feat, 128, wcat + 24960, g4, b4, 256, 1);

    // ---- final conv 512x512 fused with stats + max/min ----
    dim3 g5g(64, 4, 1);
    sgemm128<2><<<g5g, 256>>>(feat, 512, w5, 512, 512, 0);
    stats_kernel<<<1, 512>>>(g5, b5, (float)(BB*NN), 512, 0);
    emb_kernel<<<BB, 256>>>(wemb, out);
}

// round 5
// speedup vs baseline: 3.4567x; 1.0983x over previous
#include <cuda_runtime.h>
#include <math.h>
#include <float.h>

#define BB 8
#define NN 1024
#define KNN 20

// ---------------- static device scratch ----------------
__device__ float    g_G[(size_t)BB*NN*NN];        // pairwise 2*dot - sq[m]
__device__ float    g_SQ[BB*NN];
__device__ int      g_IDX[BB*NN*KNN];
__device__ float    g_Z2[(size_t)BB*NN*512];      // [bn][2O]: Zn | Zc
__device__ float    g_FEAT[(size_t)BB*NN*512];    // concat features (bn, c)
__device__ float    g_YMAX[(size_t)BB*NN*256];
__device__ float    g_YMIN[(size_t)BB*NN*256];
__device__ double   g_SUM[512];
__device__ double   g_SUMSQ[512];
__device__ float    g_A[512];
__device__ float    g_Cc[512];
__device__ float    g_WCAT[90496];                // [Wn ; Wc-Wn] per block
__device__ unsigned g_MXU[BB*512];
__device__ unsigned g_MNU[BB*512];

__device__ __forceinline__ unsigned encf(float f) {
    unsigned b = __float_as_uint(f);
    return (b & 0x80000000u) ? ~b : (b | 0x80000000u);
}
__device__ __forceinline__ float decf(unsigned u) {
    return __uint_as_float((u & 0x80000000u) ? (u & 0x7FFFFFFFu) : ~u);
}

// WCAT offsets: b1:0 (128x3), b2:384 (128x64), b3:8576 (256x64), b4:24960 (512x128)
__global__ void prep_kernel(const float* __restrict__ w1, const float* __restrict__ w2,
                            const float* __restrict__ w3, const float* __restrict__ w4) {
    int t = blockIdx.x * blockDim.x + threadIdx.x;
    if (t < 384) {
        int r = t/3, c = t%3;
        g_WCAT[t] = (r < 64) ? w1[r*6 + c] : (w1[(r-64)*6 + 3 + c] - w1[(r-64)*6 + c]);
        return;
    }
    int u = t - 384;
    if (u < 8192) {
        int r = u/64, c = u%64;
        g_WCAT[384 + u] = (r < 64) ? w2[r*128 + c] : (w2[(r-64)*128 + 64 + c] - w2[(r-64)*128 + c]);
        return;
    }
    u -= 8192;
    if (u < 16384) {
        int r = u/64, c = u%64;
        g_WCAT[8576 + u] = (r < 128) ? w3[r*128 + c] : (w3[(r-128)*128 + 64 + c] - w3[(r-128)*128 + c]);
        return;
    }
    u -= 16384;
    if (u < 65536) {
        int r = u/128, c = u%128;
        g_WCAT[24960 + u] = (r < 256) ? w4[r*256 + c] : (w4[(r-256)*256 + 128 + c] - w4[(r-256)*256 + c]);
        return;
    }
}

template<int C>
__global__ void sq_kernel(const float* __restrict__ X, int ld, int off) {
    int i = blockIdx.x * blockDim.x + threadIdx.x;
    if (i >= BB*NN) return;
    const float* p = X + (size_t)i*ld + off;
    float s = 0.f;
    #pragma unroll
    for (int c = 0; c < C; c++) s = fmaf(p[c], p[c], s);
    g_SQ[i] = s;
}

// =======================================================================
// Symmetric gram (reg-prefetch pipelined): block per (i<=j) tile pair.
// =======================================================================
__global__ void __launch_bounds__(256, 2)
gram_sym(const float* __restrict__ A, int lda, int K) {
    __shared__ __align__(16) float sAs[16][132];
    __shared__ __align__(16) float sBs[16][132];

    int t  = threadIdx.x;
    int tx = t & 15, ty = t >> 4;
    int bz = blockIdx.z;

    int idx = blockIdx.x;
    int ib = 0;
    while (idx >= 8 - ib) { idx -= 8 - ib; ib++; }
    int jb = ib + idx;

    int arow0 = ib * 128;
    int brow0 = jb * 128;
    const float* Abase = A + (size_t)(bz*1024 + arow0) * lda;
    const float* Bbase = A + (size_t)(bz*1024 + brow0) * lda;

    float acc[8][8];
    #pragma unroll
    for (int i = 0; i < 8; i++)
        #pragma unroll
        for (int j = 0; j < 8; j++) acc[i][j] = 0.f;

    int lrow[2], lq[2];
    #pragma unroll
    for (int rr = 0; rr < 2; rr++) { int f = t + rr*256; lrow[rr] = f >> 2; lq[rr] = f & 3; }

    float4 va[2], vb[2];
    #pragma unroll
    for (int rr = 0; rr < 2; rr++) {
        va[rr] = *(const float4*)(Abase + (size_t)lrow[rr]*lda + lq[rr]*4);
        vb[rr] = *(const float4*)(Bbase + (size_t)lrow[rr]*lda + lq[rr]*4);
    }

    for (int kt = 0; kt < K; kt += 16) {
        #pragma unroll
        for (int rr = 0; rr < 2; rr++) {
            sAs[lq[rr]*4+0][lrow[rr]] = va[rr].x; sAs[lq[rr]*4+1][lrow[rr]] = va[rr].y;
            sAs[lq[rr]*4+2][lrow[rr]] = va[rr].z; sAs[lq[rr]*4+3][lrow[rr]] = va[rr].w;
            sBs[lq[rr]*4+0][lrow[rr]] = vb[rr].x; sBs[lq[rr]*4+1][lrow[rr]] = vb[rr].y;
            sBs[lq[rr]*4+2][lrow[rr]] = vb[rr].z; sBs[lq[rr]*4+3][lrow[rr]] = vb[rr].w;
        }
        __syncthreads();
        if (kt + 16 < K) {
            #pragma unroll
            for (int rr = 0; rr < 2; rr++) {
                va[rr] = *(const float4*)(Abase + (size_t)lrow[rr]*lda + kt + 16 + lq[rr]*4);
                vb[rr] = *(const float4*)(Bbase + (size_t)lrow[rr]*lda + kt + 16 + lq[rr]*4);
            }
        }
        #pragma unroll
        for (int k = 0; k < 16; k++) {
            float4 a0 = *(const float4*)&sAs[k][ty*8];
            float4 a1 = *(const float4*)&sAs[k][ty*8 + 4];
            float4 b0 = *(const float4*)&sBs[k][tx*8];
            float4 b1 = *(const float4*)&sBs[k][tx*8 + 4];
            float av[8] = {a0.x, a0.y, a0.z, a0.w, a1.x, a1.y, a1.z, a1.w};
            float bv[8] = {b0.x, b0.y, b0.z, b0.w, b1.x, b1.y, b1.z, b1.w};
            #pragma unroll
            for (int i = 0; i < 8; i++)
                #pragma unroll
                for (int j = 0; j < 8; j++) acc[i][j] = fmaf(av[i], bv[j], acc[i][j]);
        }
        __syncthreads();
    }

    float sqa[8], sqb[8];
    #pragma unroll
    for (int i = 0; i < 8; i++) sqa[i] = g_SQ[bz*1024 + arow0 + ty*8 + i];
    #pragma unroll
    for (int j = 0; j < 8; j++) sqb[j] = g_SQ[bz*1024 + brow0 + tx*8 + j];

    #pragma unroll
    for (int i = 0; i < 8; i++) {
        size_t base = (size_t)(bz*1024 + arow0 + ty*8 + i)*1024 + brow0 + tx*8;
        float4 o0, o1;
        o0.x = 2.f*acc[i][0]-sqb[0]; o0.y = 2.f*acc[i][1]-sqb[1];
        o0.z = 2.f*acc[i][2]-sqb[2]; o0.w = 2.f*acc[i][3]-sqb[3];
        o1.x = 2.f*acc[i][4]-sqb[4]; o1.y = 2.f*acc[i][5]-sqb[5];
        o1.z = 2.f*acc[i][6]-sqb[6]; o1.w = 2.f*acc[i][7]-sqb[7];
        *(float4*)&g_G[base]   = o0;
        *(float4*)&g_G[base+4] = o1;
    }

    if (ib != jb) {
        float (*tbuf)[132] = sAs;
        #pragma unroll
        for (int p = 0; p < 8; p++) {
            __syncthreads();
            #pragma unroll
            for (int i = 0; i < 8; i++)
                tbuf[tx][ty*8 + i] = 2.f*acc[i][p] - sqa[i];
            __syncthreads();
            int rowIdx = t >> 4;
            int seg    = t & 15;
            size_t base = (size_t)(bz*1024 + brow0 + rowIdx*8 + p)*1024 + arow0 + seg*8;
            float4 o0 = {tbuf[rowIdx][seg*8+0], tbuf[rowIdx][seg*8+1],
                         tbuf[rowIdx][seg*8+2], tbuf[rowIdx][seg*8+3]};
            float4 o1 = {tbuf[rowIdx][seg*8+4], tbuf[rowIdx][seg*8+5],
                         tbuf[rowIdx][seg*8+6], tbuf[rowIdx][seg*8+7]};
            *(float4*)&g_G[base]   = o0;
            *(float4*)&g_G[base+4] = o1;
        }
    }
}

// =======================================================================
// 128x128x16 SGEMM (NT), reg-prefetch pipelined.
// EPI 1: plain store to g_Z2. EPI 2: gemm5 fused stats.
// =======================================================================
template<int EPI>
__global__ void __launch_bounds__(256, 2)
sgemm128(const float* __restrict__ A, int lda,
         const float* __restrict__ B, int ldb,
         int K, int N2) {
    __shared__ __align__(16) float sAs[16][132];
    __shared__ __align__(16) float sBs[16][132];

    int t  = threadIdx.x;
    int tx = t & 15, ty = t >> 4;
    int arow0 = blockIdx.x*128;
    int n0    = blockIdx.y*128;

    const float* Abase = A + (size_t)arow0 * lda;
    const float* Bbase = B + (size_t)n0 * ldb;

    float acc[8][8];
    #pragma unroll
    for (int i = 0; i < 8; i++)
        #pragma unroll
        for (int j = 0; j < 8; j++) acc[i][j] = 0.f;

    int lrow[2], lq[2];
    #pragma unroll
    for (int rr = 0; rr < 2; rr++) { int f = t + rr*256; lrow[rr] = f >> 2; lq[rr] = f & 3; }

    float4 va[2], vb[2];
    #pragma unroll
    for (int rr = 0; rr < 2; rr++) {
        va[rr] = *(const float4*)(Abase + (size_t)lrow[rr]*lda + lq[rr]*4);
        vb[rr] = *(const float4*)(Bbase + (size_t)lrow[rr]*ldb + lq[rr]*4);
    }

    for (int kt = 0; kt < K; kt += 16) {
        #pragma unroll
        for (int rr = 0; rr < 2; rr++) {
            sAs[lq[rr]*4+0][lrow[rr]] = va[rr].x; sAs[lq[rr]*4+1][lrow[rr]] = va[rr].y;
            sAs[lq[rr]*4+2][lrow[rr]] = va[rr].z; sAs[lq[rr]*4+3][lrow[rr]] = va[rr].w;
            sBs[lq[rr]*4+0][lrow[rr]] = vb[rr].x; sBs[lq[rr]*4+1][lrow[rr]] = vb[rr].y;
            sBs[lq[rr]*4+2][lrow[rr]] = vb[rr].z; sBs[lq[rr]*4+3][lrow[rr]] = vb[rr].w;
        }
        __syncthreads();
        if (kt + 16 < K) {
            #pragma unroll
            for (int rr = 0; rr < 2; rr++) {
                va[rr] = *(const float4*)(Abase + (size_t)lrow[rr]*lda + kt + 16 + lq[rr]*4);
                vb[rr] = *(const float4*)(Bbase + (size_t)lrow[rr]*ldb + kt + 16 + lq[rr]*4);
            }
        }
        #pragma unroll
        for (int k = 0; k < 16; k++) {
            float4 a0 = *(const float4*)&sAs[k][ty*8];
            float4 a1 = *(const float4*)&sAs[k][ty*8 + 4];
            float4 b0 = *(const float4*)&sBs[k][tx*8];
            float4 b1 = *(const float4*)&sBs[k][tx*8 + 4];
            float av[8] = {a0.x, a0.y, a0.z, a0.w, a1.x, a1.y, a1.z, a1.w};
            float bv[8] = {b0.x, b0.y, b0.z, b0.w, b1.x, b1.y, b1.z, b1.w};
            #pragma unroll
            for (int i = 0; i < 8; i++)
                #pragma unroll
                for (int j = 0; j < 8; j++) acc[i][j] = fmaf(av[i], bv[j], acc[i][j]);
        }
        __syncthreads();
    }

    if (EPI == 1) {
        #pragma unroll
        for (int i = 0; i < 8; i++) {
            size_t base = (size_t)(arow0 + ty*8 + i)*N2 + n0 + tx*8;
            float4 o0 = {acc[i][0], acc[i][1], acc[i][2], acc[i][3]};
            float4 o1 = {acc[i][4], acc[i][5], acc[i][6], acc[i][7]};
            *(float4*)&g_Z2[base]   = o0;
            *(float4*)&g_Z2[base+4] = o1;
        }
    } else {
        double*   ssum = reinterpret_cast<double*>(&sAs[0][0]);
        double*   ssq  = ssum + 128;
        unsigned* smx  = reinterpret_cast<unsigned*>(ssq + 128);
        unsigned* smn  = smx + 128;
        if (t < 128) { ssum[t] = 0.0; ssq[t] = 0.0; smx[t] = 0u; smn[t] = 0xFFFFFFFFu; }
        __syncthreads();
        #pragma unroll
        for (int j = 0; j < 8; j++) {
            float s = 0.f, s2 = 0.f, mx = -FLT_MAX, mn = FLT_MAX;
            #pragma unroll
            for (int i = 0; i < 8; i++) {
                float y = acc[i][j];
                s += y; s2 = fmaf(y, y, s2);
                mx = fmaxf(mx, y); mn = fminf(mn, y);
            }
            int col = tx*8 + j;
            atomicAdd(&ssum[col], (double)s);
            atomicAdd(&ssq[col],  (double)s2);
            atomicMax(&smx[col], encf(mx));
            atomicMin(&smn[col], encf(mn));
        }
        __syncthreads();
        if (t < 128) {
            int o = n0 + t;
            int b = arow0 >> 10;
            atomicAdd(&g_SUM[o],   ssum[t]);
            atomicAdd(&g_SUMSQ[o], ssq[t]);
            atomicMax(&g_MXU[b*512 + o], smx[t]);
            atomicMin(&g_MNU[b*512 + o], smn[t]);
        }
    }
}

// ---------------- stage-1 zgemm (C=3) ----------------
template<int C, int N2>
__global__ void zgemm_kernel(const float* __restrict__ X, int ld, int off,
                             const float* __restrict__ W) {
    constexpr int TC = (C < 32) ? C : 32;
    __shared__ float As[64][TC+1];
    __shared__ float Bs[64][TC+1];
    int r0 = blockIdx.x * 64;
    int o0 = blockIdx.y * 64;
    int tx = threadIdx.x & 15, ty = threadIdx.x >> 4;
    float acc[4][4];
    #pragma unroll
    for (int i = 0; i < 4; i++)
        #pragma unroll
        for (int j = 0; j < 4; j++) acc[i][j] = 0.f;
    for (int c0 = 0; c0 < C; c0 += TC) {
        for (int i = threadIdx.x; i < 64*TC; i += 256) {
            int r = i / TC, c = i - r*TC;
            As[r][c] = X[(size_t)(r0 + r)*ld + off + c0 + c];
            Bs[r][c] = W[(size_t)(o0 + r)*C + c0 + c];
        }
        __syncthreads();
        for (int c = 0; c < TC; c++) {
            float av[4], bv[4];
            #pragma unroll
            for (int i = 0; i < 4; i++) { av[i] = As[ty*4+i][c]; bv[i] = Bs[tx*4+i][c]; }
            #pragma unroll
            for (int i = 0; i < 4; i++)
                #pragma unroll
                for (int j = 0; j < 4; j++) acc[i][j] = fmaf(av[i], bv[j], acc[i][j]);
        }
        __syncthreads();
    }
    #pragma unroll
    for (int i = 0; i < 4; i++)
        #pragma unroll
        for (int j = 0; j < 4; j++)
            g_Z2[(size_t)(r0 + ty*4 + i)*N2 + o0 + tx*4 + j] = acc[i][j];
}

// ---------------- stage-1 fused distances + top-20 ----------------
__global__ void topk1_kernel(const float* __restrict__ x) {
    __shared__ float spx[1024], spy[1024], spz[1024], ssq[1024];
    int n0 = blockIdx.x * 8;
    int b  = n0 >> 10;
    int t  = threadIdx.x;
    const float* xb = x + (size_t)b * 3072;
    for (int m = t; m < 1024; m += 256) {
        float px = xb[m*3], py = xb[m*3+1], pz = xb[m*3+2];
        spx[m] = px; spy[m] = py; spz[m] = pz;
        ssq[m] = fmaf(px, px, fmaf(py, py, pz*pz));
    }
    __syncthreads();

    int warp = t >> 5, l = t & 31;
    int ln = (n0 & 1023) + warp;
    float dnx = 2.f*spx[ln], dny = 2.f*spy[ln], dnz = 2.f*spz[ln];

    float v[32];
    #pragma unroll
    for (int s = 0; s < 32; s++) {
        int m = s*32 + l;
        v[s] = fmaf(dnx, spx[m], fmaf(dny, spy[m], fmaf(dnz, spz[m], -ssq[m])));
    }

    float m1 = -FLT_MAX, m2 = -FLT_MAX;
    int s1 = 0, s2 = 0;
    #pragma unroll
    for (int s = 0; s < 32; s++) {
        float xv = v[s];
        if (xv > m2) {
            if (xv > m1) { m2 = m1; s2 = s1; m1 = xv; s1 = s; }
            else         { m2 = xv; s2 = s; }
        }
    }
    bool dirty = false;
    int row = n0 + warp;
    for (int j = 0; j < KNN; j++) {
        float bv = m1;
        int   bm = (s1 << 5) | l;
        #pragma unroll
        for (int o = 16; o; o >>= 1) {
            float ov = __shfl_xor_sync(0xFFFFFFFFu, bv, o);
            int   om = __shfl_xor_sync(0xFFFFFFFFu, bm, o);
            if (ov > bv || (ov == bv && om < bm)) { bv = ov; bm = om; }
        }
        if (l == 0) g_IDX[row*KNN + j] = bm;
        if ((bm & 31) == l) {
            #pragma unroll
            for (int s = 0; s < 32; s++) if (s == s1) v[s] = -FLT_MAX;
            if (!dirty) { m1 = m2; s1 = s2; dirty = true; }
            else {
                m1 = -FLT_MAX; m2 = -FLT_MAX; s1 = 0; s2 = 0;
                #pragma unroll
                for (int s = 0; s < 32; s++) {
                    float xv = v[s];
                    if (xv > m2) {
                        if (xv > m1) { m2 = m1; s2 = s1; m1 = xv; s1 = s; }
                        else         { m2 = xv; s2 = s; }
                    }
                }
                dirty = false;
            }
        }
    }
}

// ---------------- top-20 from g_G (stages 2-4) ----------------
__global__ void topk_kernel() {
    int warp = (blockIdx.x << 3) + (threadIdx.x >> 5);
    int l = threadIdx.x & 31;
    const float* grow = g_G + (size_t)warp * NN;
    float v[32];
    #pragma unroll
    for (int s = 0; s < 32; s++) v[s] = grow[s*32 + l];

    float m1 = -FLT_MAX, m2 = -FLT_MAX;
    int s1 = 0, s2 = 0;
    #pragma unroll
    for (int s = 0; s < 32; s++) {
        float x = v[s];
        if (x > m2) {
            if (x > m1) { m2 = m1; s2 = s1; m1 = x; s1 = s; }
            else        { m2 = x;  s2 = s; }
        }
    }
    bool dirty = false;

    for (int j = 0; j < KNN; j++) {
        float bv = m1;
        int   bm = (s1 << 5) | l;
        #pragma unroll
        for (int o = 16; o; o >>= 1) {
            float ov = __shfl_xor_sync(0xFFFFFFFFu, bv, o);
            int   om = __shfl_xor_sync(0xFFFFFFFFu, bm, o);
            if (ov > bv || (ov == bv && om < bm)) { bv = ov; bm = om; }
        }
        if (l == 0) g_IDX[warp*KNN + j] = bm;
        if ((bm & 31) == l) {
            #pragma unroll
            for (int s = 0; s < 32; s++) if (s == s1) v[s] = -FLT_MAX;
            if (!dirty) { m1 = m2; s1 = s2; dirty = true; }
            else {
                m1 = -FLT_MAX; m2 = -FLT_MAX; s1 = 0; s2 = 0;
                #pragma unroll
                for (int s = 0; s < 32; s++) {
                    float x = v[s];
                    if (x > m2) {
                        if (x > m1) { m2 = m1; s2 = s1; m1 = x; s1 = s; }
                        else        { m2 = x;  s2 = s; }
                    }
                }
                dirty = false;
            }
        }
    }
}

// ---------------- gather + k-reduce: float4 per thread, smem stats ----------------
template<int O>
__global__ void gather_kernel() {
    constexpr int TP  = O / 4;        // threads per point
    constexpr int PPB = 256 / TP;     // points per block
    __shared__ int   sidx[PPB*KNN];
    __shared__ float ssum[O], ssq2[O];

    int n0 = blockIdx.x * PPB;
    int b  = n0 >> 10;
    int t  = threadIdx.x;
    if (t < O) { ssum[t] = 0.f; ssq2[t] = 0.f; }
    for (int i = t; i < PPB*KNN; i += 256) sidx[i] = g_IDX[n0*KNN + i];
    __syncthreads();

    int p  = t / TP;
    int cg = (t % TP) * 4;
    int n  = n0 + p;
    const float* Zb = g_Z2 + ((size_t)b << 10) * (2*O);

    float4 ctr = *(const float4*)&g_Z2[(size_t)n*(2*O) + O + cg];
    float4 mx = {-FLT_MAX, -FLT_MAX, -FLT_MAX, -FLT_MAX};
    float4 mn = { FLT_MAX,  FLT_MAX,  FLT_MAX,  FLT_MAX};
    float4 s  = {0.f, 0.f, 0.f, 0.f};
    float4 s2 = {0.f, 0.f, 0.f, 0.f};

    #pragma unroll
    for (int j = 0; j < KNN; j++) {
        int m = sidx[p*KNN + j];
        float4 z = *(const float4*)&Zb[(size_t)m*(2*O) + cg];
        mx.x = fmaxf(mx.x, z.x); mn.x = fminf(mn.x, z.x); s.x += z.x; s2.x = fmaf(z.x, z.x, s2.x);
        mx.y = fmaxf(mx.y, z.y); mn.y = fminf(mn.y, z.y); s.y += z.y; s2.y = fmaf(z.y, z.y, s2.y);
        mx.z = fmaxf(mx.z, z.z); mn.z = fminf(mn.z, z.z); s.z += z.z; s2.z = fmaf(z.z, z.z, s2.z);
        mx.w = fmaxf(mx.w, z.w); mn.w = fminf(mn.w, z.w); s.w += z.w; s2.w = fmaf(z.w, z.w, s2.w);
    }

    float4 omx = {mx.x + ctr.x, mx.y + ctr.y, mx.z + ctr.z, mx.w + ctr.w};
    float4 omn = {mn.x + ctr.x, mn.y + ctr.y, mn.z + ctr.z, mn.w + ctr.w};
    *(float4*)&g_YMAX[(size_t)n*O + cg] = omx;
    *(float4*)&g_YMIN[(size_t)n*O + cg] = omn;

    const float KF = (float)KNN;
    atomicAdd(&ssum[cg+0], s.x + KF*ctr.x);
    atomicAdd(&ssum[cg+1], s.y + KF*ctr.y);
    atomicAdd(&ssum[cg+2], s.z + KF*ctr.z);
    atomicAdd(&ssum[cg+3], s.w + KF*ctr.w);
    atomicAdd(&ssq2[cg+0], s2.x + 2.f*ctr.x*s.x + KF*ctr.x*ctr.x);
    atomicAdd(&ssq2[cg+1], s2.y + 2.f*ctr.y*s.y + KF*ctr.y*ctr.y);
    atomicAdd(&ssq2[cg+2], s2.z + 2.f*ctr.z*s.z + KF*ctr.z*ctr.z);
    atomicAdd(&ssq2[cg+3], s2.w + 2.f*ctr.w*s.w + KF*ctr.w*ctr.w);
    __syncthreads();
    if (t < O) {
        atomicAdd(&g_SUM[t],   (double)ssum[t]);
        atomicAdd(&g_SUMSQ[t], (double)ssq2[t]);
    }
}

// ---------------- BN affine coeffs; self-resets accumulators ----------------
__global__ void stats_kernel(const float* __restrict__ g, const float* __restrict__ beta,
                             float count, int O, int resetMM) {
    int o = threadIdx.x;
    if (resetMM) {
        for (int i = o; i < BB*512; i += 512) { g_MXU[i] = 0u; g_MNU[i] = 0xFFFFFFFFu; }
    }
    if (o >= O) return;
    double m   = g_SUM[o]   / (double)count;
    double var = g_SUMSQ[o] / (double)count - m*m;
    float a = g[o] / sqrtf((float)var + 1e-5f);
    g_A[o]  = a;
    g_Cc[o] = beta[o] - (float)m * a;
    g_SUM[o] = 0.0; g_SUMSQ[o] = 0.0;
}

__global__ void apply_kernel(int O, int outOff) {
    int i = blockIdx.x * blockDim.x + threadIdx.x;
    if (i >= BB*NN*O) return;
    int o  = i % O;
    int bn = i / O;
    float a = g_A[o], c = g_Cc[o];
    float sel = (a >= 0.f) ? g_YMAX[i] : g_YMIN[i];
    float v = fmaf(a, sel, c);
    g_FEAT[(size_t)bn*512 + outOff + o] = (v >= 0.f) ? v : 0.2f*v;
}

// ---------------- final norm + global max + embedding ----------------
__global__ void emb_kernel(const float* __restrict__ wemb, float* __restrict__ out) {
    __shared__ float feat[512];
    int b = blockIdx.x, t = threadIdx.x;
    for (int o = t; o < 512; o += 256) {
        float a = g_A[o], c = g_Cc[o];
        float sel = (a >= 0.f) ? decf(g_MXU[b*512 + o]) : decf(g_MNU[b*512 + o]);
        float v = fmaf(a, sel, c);
        feat[o] = (v >= 0.f) ? v : 0.2f*v;
    }
    __syncthreads();
    const float* wr = wemb + (size_t)t * 512;
    float s = 0.f;
    for (int c = 0; c < 512; c++) s = fmaf(wr[c], feat[c], s);
    out[b*256 + t] = s;
}

// ---------------- host orchestration ----------------
template<int C, int O>
static void run_edge_big(const float* feat, int off, const float* wcat,
                         const float* g, const float* beta, int outOff, int resetMM) {
    sq_kernel<C><<<32, 256>>>(feat, 512, off);
    dim3 gg(36, 1, BB);
    gram_sym<<<gg, 256>>>(feat + off, 512, C);
    topk_kernel<<<BB*NN/8, 256>>>();
    dim3 zg(64, (2*O)/128, 1);
    sgemm128<1><<<zg, 256>>>(feat + off, 512, wcat, C, C, 2*O);
    gather_kernel<O><<<BB*NN/(256/(O/4)), 256>>>();
    stats_kernel<<<1, 512>>>(g, beta, (float)(BB*NN*KNN), O, resetMM);
    apply_kernel<<<(BB*NN*O + 255)/256, 256>>>(O, outOff);
}

extern "C" void kernel_launch(void* const* d_in, const int* in_sizes, int n_in,
                              void* d_out, int out_size) {
    (void)in_sizes; (void)n_in; (void)out_size;
    const float* x    = (const float*)d_in[0];
    const float* w1   = (const float*)d_in[1];
    const float* g1   = (const float*)d_in[2];
    const float* b1   = (const float*)d_in[3];
    const float* w2   = (const float*)d_in[4];
    const float* g2   = (const float*)d_in[5];
    const float* b2   = (const float*)d_in[6];
    const float* w3   = (const float*)d_in[7];
    const float* g3   = (const float*)d_in[8];
    const float* b3   = (const float*)d_in[9];
    const float* w4   = (const float*)d_in[10];
    const float* g4   = (const float*)d_in[11];
    const float* b4   = (const float*)d_in[12];
    const float* w5   = (const float*)d_in[13];
    const float* g5   = (const float*)d_in[14];
    const float* b5   = (const float*)d_in[15];
    const float* wemb = (const float*)d_in[16];
    float* out = (float*)d_out;

    float *feat, *wcat;
    cudaGetSymbolAddress((void**)&feat, g_FEAT);
    cudaGetSymbolAddress((void**)&wcat, g_WCAT);

    prep_kernel<<<(90496 + 255)/256, 256>>>(w1, w2, w3, w4);

    // ---- stage 1 (C=3): fused distance + topk, small zgemm ----
    topk1_kernel<<<BB*NN/8, 256>>>(x);
    dim3 zg1(BB*NN/64, 2);
    zgemm_kernel<3, 128><<<zg1, 256>>>(x, 3, 0, wcat);
    gather_kernel<64><<<BB*NN/16, 256>>>();
    stats_kernel<<<1, 512>>>(g1, b1, (float)(BB*NN*KNN), 64, 0);
    apply_kernel<<<(BB*NN*64 + 255)/256, 256>>>(64, 0);

    // ---- stages 2-4: symmetric gram + SGEMM path ----
    run_edge_big<64,  64 >(feat, 0,   wcat + 384,   g2, b2, 64, 0);
    run_edge_big<64,  128>(feat, 64,  wcat + 8576,  g3, b3, 128, 0);
    run_edge_big<128, 256>(feat, 128, wcat + 24960, g4, b4, 256, 1);

    // ---- final conv 512x512 fused with stats + max/min ----
    dim3 g5g(64, 4, 1);
    sgemm128<2><<<g5g, 256>>>(feat, 512, w5, 512, 512, 0);
    stats_kernel<<<1, 512>>>(g5, b5, (float)(BB*NN), 512, 0);
    emb_kernel<<<BB, 256>>>(wemb, out);
}